// round 11
// baseline (speedup 1.0000x reference)
#include <cuda_runtime.h>
#include <cuda_bf16.h>
#include <cstdint>

#define N_NODES 50000
#define PAD_M   50048
#define N_EDGES 300000
#define DIN     1024
#define DHID    512
#define DOUT    30
#define NEG_SLOPE 0.2f

// ---------------- scratch (static device globals; zero-initialized at load) ----------------
__device__ __align__(16) float g_buf0[N_NODES * DHID];   // h, then g
__device__ __align__(16) float g_buf1[N_NODES * DHID];   // acc1, then acc3
__device__ float    g_escore[N_EDGES];
__device__ float    g_ex[N_EDGES];
__device__ unsigned g_mx[N_NODES];
__device__ float    g_den[N_NODES];
__device__ __align__(16) float g_w2t[DOUT * DHID];
// pre-transposed + bf16-split weights: [N][K] layout
__device__ __align__(16) __nv_bfloat16 g_w1t_hi[DHID * DIN];
__device__ __align__(16) __nv_bfloat16 g_w1t_lo[DHID * DIN];
__device__ __align__(16) __nv_bfloat16 g_w4t_hi[DIN * DHID];
__device__ __align__(16) __nv_bfloat16 g_w4t_lo[DIN * DHID];
// A-operand bf16 split (reused: features K=1024, then h3 K=512)
__device__ __align__(16) __nv_bfloat16 g_a_hi[(size_t)PAD_M * DIN];
__device__ __align__(16) __nv_bfloat16 g_a_lo[(size_t)PAD_M * DIN];

// ================= helpers =================
__device__ __forceinline__ uint32_t smem_u32(const void* p) {
    uint32_t a;
    asm("{ .reg .u64 t; cvta.to.shared.u64 t, %1; cvt.u32.u64 %0, t; }" : "=r"(a) : "l"(p));
    return a;
}
#define CP_ASYNC16(dst, src) asm volatile("cp.async.cg.shared.global [%0], [%1], 16;" :: "r"(dst), "l"(src) : "memory")
#define CP_COMMIT()          asm volatile("cp.async.commit_group;" ::: "memory")
#define CP_WAIT1()           asm volatile("cp.async.wait_group 1;" ::: "memory")
#define CP_WAIT0()           asm volatile("cp.async.wait_group 0;" ::: "memory")

__device__ __forceinline__ void ldsm_x4(uint32_t& r0, uint32_t& r1, uint32_t& r2, uint32_t& r3, uint32_t a) {
    asm volatile("ldmatrix.sync.aligned.m8n8.x4.shared.b16 {%0,%1,%2,%3}, [%4];"
                 : "=r"(r0), "=r"(r1), "=r"(r2), "=r"(r3) : "r"(a));
}
__device__ __forceinline__ void mma16816(float* c, const uint32_t* a, const uint32_t* b) {
    asm volatile("mma.sync.aligned.m16n8k16.row.col.f32.bf16.bf16.f32 "
                 "{%0,%1,%2,%3}, {%4,%5,%6,%7}, {%8,%9}, {%0,%1,%2,%3};"
                 : "+f"(c[0]), "+f"(c[1]), "+f"(c[2]), "+f"(c[3])
                 : "r"(a[0]), "r"(a[1]), "r"(a[2]), "r"(a[3]), "r"(b[0]), "r"(b[1]));
}
__device__ __forceinline__ void split2(float x, float y, uint32_t& hi, uint32_t& lo) {
    __nv_bfloat16 hx = __float2bfloat16(x);
    __nv_bfloat16 hy = __float2bfloat16(y);
    __nv_bfloat16 lx = __float2bfloat16(x - __bfloat162float(hx));
    __nv_bfloat16 ly = __float2bfloat16(y - __bfloat162float(hy));
    hi = ((uint32_t)__bfloat16_as_ushort(hy) << 16) | (uint32_t)__bfloat16_as_ushort(hx);
    lo = ((uint32_t)__bfloat16_as_ushort(ly) << 16) | (uint32_t)__bfloat16_as_ushort(lx);
}

// ================= bf16-split tensor-core GEMM =================
// C[M,N] = A[M,K] @ B[K,N]; A hi/lo bf16 [M][K]; B hi/lo bf16 [N][K].
// CTA tile 128x128, warp tile 64x32 (8 warps), K staged 32, double-buffered cp.async.
// Pass-major inner loop: 16 independent MMAs between successive writes to the
// same accumulator (breaks the 3-pass serialization on HMMA latency).
#define SROWB   80
#define MATB    (128 * SROWB)       // 10240
#define STG_BYTES (4 * MATB)        // 40960

#define LOAD_STAGE(bufbase, k0)                                                       \
    _Pragma("unroll")                                                                 \
    for (int q = 0; q < 8; q++) {                                                     \
        int c = tid + q * 256;                                                        \
        int mat = c >> 9, row = (c >> 2) & 127, cc = c & 3;                           \
        uint32_t dstp = (bufbase) + mat * MATB + row * SROWB + cc * 16;               \
        const __nv_bfloat16* srcp;                                                    \
        if (mat == 0)      srcp = Ahi + (size_t)(mtile * 128 + row) * K + (k0) + cc * 8; \
        else if (mat == 1) srcp = Alo + (size_t)(mtile * 128 + row) * K + (k0) + cc * 8; \
        else if (mat == 2) srcp = Bhi + (size_t)(ntile * 128 + row) * K + (k0) + cc * 8; \
        else               srcp = Blo + (size_t)(ntile * 128 + row) * K + (k0) + cc * 8; \
        CP_ASYNC16(dstp, srcp);                                                       \
    }

__global__ __launch_bounds__(256, 2) void k_mma_gemm(const __nv_bfloat16* __restrict__ Ahi,
                                                     const __nv_bfloat16* __restrict__ Alo,
                                                     const __nv_bfloat16* __restrict__ Bhi,
                                                     const __nv_bfloat16* __restrict__ Blo,
                                                     float* __restrict__ C,
                                                     int M, int K, int N) {
    extern __shared__ char smem[];
    const int tid = threadIdx.x;
    const int lane = tid & 31, wid = tid >> 5;
    const int wm = (wid & 1) * 64, wn = (wid >> 1) * 32;
    const int mtile = blockIdx.y, ntile = blockIdx.x;
    const int nstages = K >> 5;
    const uint32_t sb = smem_u32(smem);

    float acc[4][4][4];
#pragma unroll
    for (int i = 0; i < 4; i++)
#pragma unroll
        for (int j = 0; j < 4; j++)
#pragma unroll
            for (int t = 0; t < 4; t++) acc[i][j][t] = 0.f;

    LOAD_STAGE(sb, 0);
    CP_COMMIT();

    const int ar = lane & 15, ac = (lane >> 4) * 8;
    const int bnr = ((lane >> 4) * 8) + (lane & 7);
    const int bkc = ((lane >> 3) & 1) * 8;

    for (int s = 0; s < nstages; s++) {
        if (s + 1 < nstages) {
            LOAD_STAGE(sb + (uint32_t)(((s + 1) & 1) * STG_BYTES), (s + 1) * 32);
            CP_COMMIT();
            CP_WAIT1();
        } else {
            CP_WAIT0();
        }
        __syncthreads();
        const uint32_t st = sb + (uint32_t)((s & 1) * STG_BYTES);
#pragma unroll
        for (int ks = 0; ks < 2; ks++) {
            uint32_t bh[4][2], bl[4][2], ah[4][4], al[4][4];
            // B-hi fragments (2 x ldmatrix.x4 -> 4 n-groups x 2 k-halves)
#pragma unroll
            for (int jp = 0; jp < 2; jp++) {
                uint32_t baddr = st + 2u * MATB +
                    (uint32_t)((wn + jp * 16 + bnr) * SROWB + (ks * 16 + bkc) * 2);
                ldsm_x4(bh[jp * 2][0], bh[jp * 2][1], bh[jp * 2 + 1][0], bh[jp * 2 + 1][1], baddr);
            }
            // A-hi fragments
#pragma unroll
            for (int i = 0; i < 4; i++) {
                uint32_t aaddr = st + (uint32_t)((wm + i * 16 + ar) * SROWB + (ks * 16 + ac) * 2);
                ldsm_x4(ah[i][0], ah[i][1], ah[i][2], ah[i][3], aaddr);
            }
            // pass 1: Ah * Bh  (16 independent MMAs)
#pragma unroll
            for (int i = 0; i < 4; i++)
#pragma unroll
                for (int j = 0; j < 4; j++) mma16816(acc[i][j], ah[i], bh[j]);
            // B-lo fragments
#pragma unroll
            for (int jp = 0; jp < 2; jp++) {
                uint32_t baddr = st + 3u * MATB +
                    (uint32_t)((wn + jp * 16 + bnr) * SROWB + (ks * 16 + bkc) * 2);
                ldsm_x4(bl[jp * 2][0], bl[jp * 2][1], bl[jp * 2 + 1][0], bl[jp * 2 + 1][1], baddr);
            }
            // pass 2: Ah * Bl
#pragma unroll
            for (int i = 0; i < 4; i++)
#pragma unroll
                for (int j = 0; j < 4; j++) mma16816(acc[i][j], ah[i], bl[j]);
            // A-lo fragments
#pragma unroll
            for (int i = 0; i < 4; i++) {
                uint32_t aaddr = st + 1u * MATB +
                    (uint32_t)((wm + i * 16 + ar) * SROWB + (ks * 16 + ac) * 2);
                ldsm_x4(al[i][0], al[i][1], al[i][2], al[i][3], aaddr);
            }
            // pass 3: Al * Bh
#pragma unroll
            for (int i = 0; i < 4; i++)
#pragma unroll
                for (int j = 0; j < 4; j++) mma16816(acc[i][j], al[i], bh[j]);
        }
        __syncthreads();
    }
    // epilogue
    const int r0 = lane >> 2, cq = (lane & 3) * 2;
#pragma unroll
    for (int i = 0; i < 4; i++) {
#pragma unroll
        for (int j = 0; j < 4; j++) {
            int gr = mtile * 128 + wm + i * 16 + r0;
            int gc = ntile * 128 + wn + j * 8 + cq;
            if (gr < M) *(float2*)&C[(size_t)gr * N + gc] = make_float2(acc[i][j][0], acc[i][j][1]);
            if (gr + 8 < M) *(float2*)&C[(size_t)(gr + 8) * N + gc] = make_float2(acc[i][j][2], acc[i][j][3]);
        }
    }
}

// ---------------- fused weight prep: W1 split+T, W4 split+T, W2 transpose ----------------
#define PREP_W1 (DIN * DHID)
#define PREP_W4 (DHID * DIN)
#define PREP_W2 (DHID * DOUT)
__global__ void k_prep_all(const float* __restrict__ W1, const float* __restrict__ W4,
                           const float* __restrict__ W2) {
    int i = blockIdx.x * blockDim.x + threadIdx.x;
    if (i < PREP_W1) {
        int k = i / DHID, n = i % DHID;
        float x = W1[i];
        __nv_bfloat16 h = __float2bfloat16(x);
        g_w1t_hi[(size_t)n * DIN + k] = h;
        g_w1t_lo[(size_t)n * DIN + k] = __float2bfloat16(x - __bfloat162float(h));
    } else if (i < PREP_W1 + PREP_W4) {
        int j = i - PREP_W1;
        int k = j / DIN, n = j % DIN;
        float x = W4[j];
        __nv_bfloat16 h = __float2bfloat16(x);
        g_w4t_hi[(size_t)n * DHID + k] = h;
        g_w4t_lo[(size_t)n * DHID + k] = __float2bfloat16(x - __bfloat162float(h));
    } else if (i < PREP_W1 + PREP_W4 + PREP_W2) {
        int j = i - PREP_W1 - PREP_W4;
        int col = j / DOUT, k = j % DOUT;
        g_w2t[k * DHID + col] = W2[j];
    }
}

// ---------------- A split: fp32 -> bf16 hi/lo ----------------
__global__ void k_split_a(const float* __restrict__ X, __nv_bfloat16* __restrict__ hi,
                          __nv_bfloat16* __restrict__ lo, int n2) {
    int i = blockIdx.x * blockDim.x + threadIdx.x;
    if (i >= n2) return;
    float2 v = ((const float2*)X)[i];
    uint32_t hp, lp;
    split2(v.x, v.y, hp, lp);
    ((uint32_t*)hi)[i] = hp;
    ((uint32_t*)lo)[i] = lp;
}

// ---------------- (acc/den) -> elu -> split  (for h3; per-node denominator) ----------------
__global__ void k_elu_split(const float* __restrict__ X, __nv_bfloat16* __restrict__ hi,
                            __nv_bfloat16* __restrict__ lo, int n2) {
    int i = blockIdx.x * blockDim.x + threadIdx.x;
    if (i >= n2) return;
    int node = i / (DHID / 2);
    float dn = g_den[node];
    float w = dn > 0.f ? __fdividef(1.f, dn) : 0.f;
    float2 v = ((const float2*)X)[i];
    v.x *= w; v.y *= w;
    v.x = v.x > 0.f ? v.x : expm1f(v.x);
    v.y = v.y > 0.f ? v.y : expm1f(v.y);
    uint32_t hp, lp;
    split2(v.x, v.y, hp, lp);
    ((uint32_t*)hi)[i] = hp;
    ((uint32_t*)lo)[i] = lp;
}

// ---------------- init ----------------
__global__ void k_init() {
    size_t i = blockIdx.x * (size_t)blockDim.x + threadIdx.x;
    size_t stride = (size_t)gridDim.x * blockDim.x;
    float4 z = make_float4(0.f, 0.f, 0.f, 0.f);
    float4* a1 = (float4*)g_buf1;
    const size_t n4 = (size_t)N_NODES * DHID / 4;
    for (size_t j = i; j < n4; j += stride) a1[j] = z;
    for (size_t j = i; j < N_NODES; j += stride) { g_den[j] = 0.f; g_mx[j] = 0u; }
}

// ---------------- edge scores ----------------
__global__ __launch_bounds__(256) void k_edge_score(const int* __restrict__ src,
                                                    const int* __restrict__ dst,
                                                    const float* __restrict__ h,
                                                    const float* __restrict__ att) {
    int e = (int)((blockIdx.x * (size_t)blockDim.x + threadIdx.x) >> 5);
    int lane = threadIdx.x & 31;
    if (e >= N_EDGES) return;
    int s = src[e], d = dst[e];
    const float4* hs = (const float4*)(h + (size_t)s * DHID);
    const float4* hd = (const float4*)(h + (size_t)d * DHID);
    const float4* at = (const float4*)att;
    float sum = 0.f;
#pragma unroll
    for (int i = 0; i < 4; i++) {
        int idx = lane + i * 32;
        float4 a = hs[idx], b = hd[idx], t = __ldg(&at[idx]);
        float x;
        x = a.x + b.x; sum += t.x * (x > 0.f ? x : NEG_SLOPE * x);
        x = a.y + b.y; sum += t.y * (x > 0.f ? x : NEG_SLOPE * x);
        x = a.z + b.z; sum += t.z * (x > 0.f ? x : NEG_SLOPE * x);
        x = a.w + b.w; sum += t.w * (x > 0.f ? x : NEG_SLOPE * x);
    }
#pragma unroll
    for (int o = 16; o > 0; o >>= 1) sum += __shfl_xor_sync(0xffffffffu, sum, o);
    if (lane == 0) {
        g_escore[e] = sum;
        unsigned enc = __float_as_uint(sum);
        enc = (enc & 0x80000000u) ? ~enc : (enc | 0x80000000u);
        atomicMax(&g_mx[d], enc);
    }
}

// ---------------- scatter aggregation: Acc[dst] += w * X[src], w = exp(e - max[dst]) ----------------
// FIRST: compute w from escore/max, store to g_ex, accumulate den. !FIRST: reuse g_ex.
template <bool FIRST>
__global__ __launch_bounds__(256) void k_aggregate(const int* __restrict__ src,
                                                   const int* __restrict__ dst,
                                                   const float* __restrict__ X,
                                                   float* __restrict__ Acc) {
    int e = (int)((blockIdx.x * (size_t)blockDim.x + threadIdx.x) >> 5);
    int lane = threadIdx.x & 31;
    if (e >= N_EDGES) return;
    int s = src[e], d = dst[e];
    float w;
    if (FIRST) {
        if (lane == 0) {
            unsigned u = g_mx[d];
            unsigned b = (u & 0x80000000u) ? (u & 0x7FFFFFFFu) : ~u;
            float m = __uint_as_float(b);
            w = __expf(g_escore[e] - m);
            g_ex[e] = w;
            atomicAdd(&g_den[d], w);
        }
        w = __shfl_sync(0xffffffffu, w, 0);
    } else {
        w = g_ex[e];
    }
    const float4* xs = (const float4*)(X + (size_t)s * DHID);
    float* out = Acc + (size_t)d * DHID;
#pragma unroll
    for (int i = 0; i < 4; i++) {
        int idx = lane + i * 32;
        float4 v = xs[idx];
        float* p = out + idx * 4;
        asm volatile("red.global.add.v4.f32 [%0], {%1, %2, %3, %4};"
                     :: "l"(p), "f"(w * v.x), "f"(w * v.y), "f"(w * v.z), "f"(w * v.w)
                     : "memory");
    }
}

// ---------------- h2 = elu(acc1/den) @ W2, then re-zero acc1 rows ----------------
__global__ __launch_bounds__(256) void k_h2(float* __restrict__ acc1,
                                            const float* __restrict__ W2,
                                            float* __restrict__ out) {
    __shared__ float hs[8][DHID];
    const int tid = threadIdx.x;
    const int rowBase = blockIdx.x * 8;
    float4* srcp = (float4*)(acc1 + (size_t)rowBase * DHID);
    float4* dstp = (float4*)hs;
    for (int i = tid; i < 8 * DHID / 4; i += 256) {
        int node = rowBase + i / (DHID / 4);
        float dn = g_den[node];
        float w = dn > 0.f ? __fdividef(1.f, dn) : 0.f;
        float4 v = srcp[i];
        v.x *= w; v.y *= w; v.z *= w; v.w *= w;
        v.x = v.x > 0.f ? v.x : expm1f(v.x);
        v.y = v.y > 0.f ? v.y : expm1f(v.y);
        v.z = v.z > 0.f ? v.z : expm1f(v.z);
        v.w = v.w > 0.f ? v.w : expm1f(v.w);
        dstp[i] = v;
    }
    __syncthreads();
    int r = tid >> 5;
    int c = tid & 31;
    if (c < DOUT) {
        float acc = 0.f;
#pragma unroll 8
        for (int k = 0; k < DHID; k++) acc += hs[r][k] * __ldg(&W2[k * DOUT + c]);
        out[(size_t)(rowBase + r) * DOUT + c] = acc;
    }
    // re-zero these acc1 rows for the second aggregation
    float4 z = make_float4(0.f, 0.f, 0.f, 0.f);
    for (int i = tid; i < 8 * DHID / 4; i += 256) srcp[i] = z;
}

// ---------------- g = h2 @ W2^T ----------------
__global__ __launch_bounds__(256) void k_g(const float* __restrict__ h2,
                                           float* __restrict__ gout) {
    __shared__ float hr[DOUT];
    int row = blockIdx.y;
    int col = blockIdx.x * 256 + threadIdx.x;
    if (threadIdx.x < DOUT) hr[threadIdx.x] = __ldg(&h2[(size_t)row * DOUT + threadIdx.x]);
    __syncthreads();
    float acc = 0.f;
#pragma unroll
    for (int k = 0; k < DOUT; k++) acc += hr[k] * g_w2t[k * DHID + col];
    gout[(size_t)row * DHID + col] = acc;
}

// ---------------- launch ----------------
extern "C" void kernel_launch(void* const* d_in, const int* in_sizes, int n_in,
                              void* d_out, int out_size) {
    const float* features = (const float*)d_in[0];
    const int*   eidx     = (const int*)d_in[1];
    const float* W1       = (const float*)d_in[2];
    const float* att1     = (const float*)d_in[3];
    const float* W2       = (const float*)d_in[4];
    const float* W4       = (const float*)d_in[5];
    float* out = (float*)d_out;
    const int* src = eidx;
    const int* dst = eidx + N_EDGES;

    float *p_buf0, *p_buf1;
    __nv_bfloat16 *p_w1h, *p_w1l, *p_w4h, *p_w4l, *p_ah, *p_al;
    cudaGetSymbolAddress((void**)&p_buf0, g_buf0);
    cudaGetSymbolAddress((void**)&p_buf1, g_buf1);
    cudaGetSymbolAddress((void**)&p_w1h, g_w1t_hi);
    cudaGetSymbolAddress((void**)&p_w1l, g_w1t_lo);
    cudaGetSymbolAddress((void**)&p_w4h, g_w4t_hi);
    cudaGetSymbolAddress((void**)&p_w4l, g_w4t_lo);
    cudaGetSymbolAddress((void**)&p_ah, g_a_hi);
    cudaGetSymbolAddress((void**)&p_al, g_a_lo);

    cudaFuncSetAttribute(k_mma_gemm, cudaFuncAttributeMaxDynamicSharedMemorySize, 2 * STG_BYTES);

    float* out_h2 = out;                          // [50000, 30]
    float* out_h4 = out + (size_t)N_NODES * DOUT; // [50000, 1024]

    const int edgeBlocks = (N_EDGES * 32 + 255) / 256;
    const int mtiles = (N_NODES + 127) / 128;     // 391

    // 1) zero acc + softmax stats
    k_init<<<2048, 256>>>();
    // 2) all weight prep (one launch)
    k_prep_all<<<(PREP_W1 + PREP_W4 + PREP_W2 + 255) / 256, 256>>>(W1, W4, W2);
    // 3) split features -> a_hi/a_lo
    k_split_a<<<(N_NODES * DIN / 2 + 255) / 256, 256>>>(features, p_ah, p_al, N_NODES * DIN / 2);
    // 4) h = X @ W1 -> buf0  (tensor cores; launch #4 -> ncu-profiled)
    {
        dim3 grid(DHID / 128, mtiles);
        k_mma_gemm<<<grid, 256, 2 * STG_BYTES>>>(p_ah, p_al, p_w1h, p_w1l, p_buf0, N_NODES, DIN, DHID);
    }
    // 5) edge scores + segment max
    k_edge_score<<<edgeBlocks, 256>>>(src, dst, p_buf0, att1);
    // 6) agg1: buf1[dst] += ex * h[src]; accumulates den; stores ex
    k_aggregate<true><<<edgeBlocks, 256>>>(src, dst, p_buf0, p_buf1);
    // 7) h2 = elu(buf1/den) @ W2 -> out; re-zeros buf1
    k_h2<<<N_NODES / 8, 256>>>(p_buf1, W2, out_h2);
    // 8) g = h2 @ W2^T -> buf0
    {
        dim3 grid(DHID / 256, N_NODES);
        k_g<<<grid, 256>>>(out_h2, p_buf0);
    }
    // 9) agg2: buf1[dst] += ex * g[src]
    k_aggregate<false><<<edgeBlocks, 256>>>(src, dst, p_buf0, p_buf1);
    // 10) h3 = elu(buf1/den) fused with bf16 split -> a_hi/a_lo (K=512 layout)
    k_elu_split<<<(N_NODES * DHID / 2 + 255) / 256, 256>>>(p_buf1, p_ah, p_al, N_NODES * DHID / 2);
    // 11) h4 = h3 @ W4 -> out  (tensor cores)
    {
        dim3 grid(DIN / 128, mtiles);
        k_mma_gemm<<<grid, 256, 2 * STG_BYTES>>>(p_ah, p_al, p_w4h, p_w4l, out_h4, N_NODES, DHID, DIN);
    }
}

// round 12
// speedup vs baseline: 1.4354x; 1.4354x over previous
#include <cuda_runtime.h>
#include <cuda_bf16.h>
#include <cstdint>

#define N_NODES 50000
#define PAD_M   50048
#define N_EDGES 300000
#define DIN     1024
#define DHID    512
#define DOUT    30
#define NEG_SLOPE 0.2f

// ---------------- scratch (static device globals; zero-initialized at load) ----------------
__device__ __align__(16) float g_buf0[N_NODES * DHID];   // h, then g
__device__ __align__(16) float g_buf1[N_NODES * DHID];   // acc1, then acc3
__device__ float    g_escore[N_EDGES];
__device__ float    g_ex[N_EDGES];
__device__ unsigned g_mx[N_NODES];
__device__ float    g_den[N_NODES];
__device__ __align__(16) float g_w2t[DOUT * DHID];
// pre-transposed + bf16-split weights: [N][K] layout
__device__ __align__(16) __nv_bfloat16 g_w1t_hi[DHID * DIN];
__device__ __align__(16) __nv_bfloat16 g_w1t_lo[DHID * DIN];
__device__ __align__(16) __nv_bfloat16 g_w4t_hi[DIN * DHID];
__device__ __align__(16) __nv_bfloat16 g_w4t_lo[DIN * DHID];
// A-operand bf16 split (reused: features K=1024, then h3 K=512)
__device__ __align__(16) __nv_bfloat16 g_a_hi[(size_t)PAD_M * DIN];
__device__ __align__(16) __nv_bfloat16 g_a_lo[(size_t)PAD_M * DIN];

// ================= helpers =================
__device__ __forceinline__ uint32_t smem_u32(const void* p) {
    uint32_t a;
    asm("{ .reg .u64 t; cvta.to.shared.u64 t, %1; cvt.u32.u64 %0, t; }" : "=r"(a) : "l"(p));
    return a;
}
#define CP_ASYNC16(dst, src) asm volatile("cp.async.cg.shared.global [%0], [%1], 16;" :: "r"(dst), "l"(src) : "memory")
#define CP_COMMIT()          asm volatile("cp.async.commit_group;" ::: "memory")
#define CP_WAIT1()           asm volatile("cp.async.wait_group 1;" ::: "memory")
#define CP_WAIT0()           asm volatile("cp.async.wait_group 0;" ::: "memory")

__device__ __forceinline__ void ldsm_x4(uint32_t& r0, uint32_t& r1, uint32_t& r2, uint32_t& r3, uint32_t a) {
    asm volatile("ldmatrix.sync.aligned.m8n8.x4.shared.b16 {%0,%1,%2,%3}, [%4];"
                 : "=r"(r0), "=r"(r1), "=r"(r2), "=r"(r3) : "r"(a));
}
__device__ __forceinline__ void mma16816(float* c, const uint32_t* a, const uint32_t* b) {
    asm volatile("mma.sync.aligned.m16n8k16.row.col.f32.bf16.bf16.f32 "
                 "{%0,%1,%2,%3}, {%4,%5,%6,%7}, {%8,%9}, {%0,%1,%2,%3};"
                 : "+f"(c[0]), "+f"(c[1]), "+f"(c[2]), "+f"(c[3])
                 : "r"(a[0]), "r"(a[1]), "r"(a[2]), "r"(a[3]), "r"(b[0]), "r"(b[1]));
}
__device__ __forceinline__ void split2(float x, float y, uint32_t& hi, uint32_t& lo) {
    __nv_bfloat16 hx = __float2bfloat16(x);
    __nv_bfloat16 hy = __float2bfloat16(y);
    __nv_bfloat16 lx = __float2bfloat16(x - __bfloat162float(hx));
    __nv_bfloat16 ly = __float2bfloat16(y - __bfloat162float(hy));
    hi = ((uint32_t)__bfloat16_as_ushort(hy) << 16) | (uint32_t)__bfloat16_as_ushort(hx);
    lo = ((uint32_t)__bfloat16_as_ushort(ly) << 16) | (uint32_t)__bfloat16_as_ushort(lx);
}

// ================= bf16-split tensor-core GEMM (R10 structure) =================
// C[M,N] = A[M,K] @ B[K,N]; A hi/lo bf16 [M][K]; B hi/lo bf16 [N][K].
// CTA tile 128x128, warp tile 64x32 (8 warps), K staged 32, double-buffered cp.async.
#define SROWB   80
#define MATB    (128 * SROWB)       // 10240
#define STG_BYTES (4 * MATB)        // 40960

#define LOAD_STAGE(bufbase, k0)                                                       \
    _Pragma("unroll")                                                                 \
    for (int q = 0; q < 8; q++) {                                                     \
        int c = tid + q * 256;                                                        \
        int mat = c >> 9, row = (c >> 2) & 127, cc = c & 3;                           \
        uint32_t dstp = (bufbase) + mat * MATB + row * SROWB + cc * 16;               \
        const __nv_bfloat16* srcp;                                                    \
        if (mat == 0)      srcp = Ahi + (size_t)(mtile * 128 + row) * K + (k0) + cc * 8; \
        else if (mat == 1) srcp = Alo + (size_t)(mtile * 128 + row) * K + (k0) + cc * 8; \
        else if (mat == 2) srcp = Bhi + (size_t)(ntile * 128 + row) * K + (k0) + cc * 8; \
        else               srcp = Blo + (size_t)(ntile * 128 + row) * K + (k0) + cc * 8; \
        CP_ASYNC16(dstp, srcp);                                                       \
    }

__global__ __launch_bounds__(256, 2) void k_mma_gemm(const __nv_bfloat16* __restrict__ Ahi,
                                                     const __nv_bfloat16* __restrict__ Alo,
                                                     const __nv_bfloat16* __restrict__ Bhi,
                                                     const __nv_bfloat16* __restrict__ Blo,
                                                     float* __restrict__ C,
                                                     int M, int K, int N) {
    extern __shared__ char smem[];
    const int tid = threadIdx.x;
    const int lane = tid & 31, wid = tid >> 5;
    const int wm = (wid & 1) * 64, wn = (wid >> 1) * 32;
    const int mtile = blockIdx.y, ntile = blockIdx.x;
    const int nstages = K >> 5;
    const uint32_t sb = smem_u32(smem);

    float acc[4][4][4];
#pragma unroll
    for (int i = 0; i < 4; i++)
#pragma unroll
        for (int j = 0; j < 4; j++)
#pragma unroll
            for (int t = 0; t < 4; t++) acc[i][j][t] = 0.f;

    LOAD_STAGE(sb, 0);
    CP_COMMIT();

    const int ar = lane & 15, ac = (lane >> 4) * 8;
    const int bnr = ((lane >> 4) * 8) + (lane & 7);
    const int bkc = ((lane >> 3) & 1) * 8;

    for (int s = 0; s < nstages; s++) {
        if (s + 1 < nstages) {
            LOAD_STAGE(sb + (uint32_t)(((s + 1) & 1) * STG_BYTES), (s + 1) * 32);
            CP_COMMIT();
            CP_WAIT1();
        } else {
            CP_WAIT0();
        }
        __syncthreads();
        const uint32_t st = sb + (uint32_t)((s & 1) * STG_BYTES);
#pragma unroll
        for (int ks = 0; ks < 2; ks++) {
            uint32_t bh[4][2], bl[4][2];
#pragma unroll
            for (int jp = 0; jp < 2; jp++) {
                uint32_t baddr = st + 2u * MATB +
                    (uint32_t)((wn + jp * 16 + bnr) * SROWB + (ks * 16 + bkc) * 2);
                ldsm_x4(bh[jp * 2][0], bh[jp * 2][1], bh[jp * 2 + 1][0], bh[jp * 2 + 1][1], baddr);
                ldsm_x4(bl[jp * 2][0], bl[jp * 2][1], bl[jp * 2 + 1][0], bl[jp * 2 + 1][1], baddr + MATB);
            }
#pragma unroll
            for (int i = 0; i < 4; i++) {
                uint32_t ah[4], al[4];
                uint32_t aaddr = st + (uint32_t)((wm + i * 16 + ar) * SROWB + (ks * 16 + ac) * 2);
                ldsm_x4(ah[0], ah[1], ah[2], ah[3], aaddr);
                ldsm_x4(al[0], al[1], al[2], al[3], aaddr + MATB);
#pragma unroll
                for (int j = 0; j < 4; j++) {
                    mma16816(acc[i][j], ah, bh[j]);
                    mma16816(acc[i][j], ah, bl[j]);
                    mma16816(acc[i][j], al, bh[j]);
                }
            }
        }
        __syncthreads();
    }
    // epilogue
    const int r0 = lane >> 2, cq = (lane & 3) * 2;
#pragma unroll
    for (int i = 0; i < 4; i++) {
#pragma unroll
        for (int j = 0; j < 4; j++) {
            int gr = mtile * 128 + wm + i * 16 + r0;
            int gc = ntile * 128 + wn + j * 8 + cq;
            if (gr < M) *(float2*)&C[(size_t)gr * N + gc] = make_float2(acc[i][j][0], acc[i][j][1]);
            if (gr + 8 < M) *(float2*)&C[(size_t)(gr + 8) * N + gc] = make_float2(acc[i][j][2], acc[i][j][3]);
        }
    }
}

// ---------------- fused weight prep: W1 split+T, W4 split+T, W2 transpose ----------------
#define PREP_W1 (DIN * DHID)
#define PREP_W4 (DHID * DIN)
#define PREP_W2 (DHID * DOUT)
__global__ void k_prep_all(const float* __restrict__ W1, const float* __restrict__ W4,
                           const float* __restrict__ W2) {
    int i = blockIdx.x * blockDim.x + threadIdx.x;
    if (i < PREP_W1) {
        int k = i / DHID, n = i % DHID;
        float x = W1[i];
        __nv_bfloat16 h = __float2bfloat16(x);
        g_w1t_hi[(size_t)n * DIN + k] = h;
        g_w1t_lo[(size_t)n * DIN + k] = __float2bfloat16(x - __bfloat162float(h));
    } else if (i < PREP_W1 + PREP_W4) {
        int j = i - PREP_W1;
        int k = j / DIN, n = j % DIN;
        float x = W4[j];
        __nv_bfloat16 h = __float2bfloat16(x);
        g_w4t_hi[(size_t)n * DHID + k] = h;
        g_w4t_lo[(size_t)n * DHID + k] = __float2bfloat16(x - __bfloat162float(h));
    } else if (i < PREP_W1 + PREP_W4 + PREP_W2) {
        int j = i - PREP_W1 - PREP_W4;
        int col = j / DOUT, k = j % DOUT;
        g_w2t[k * DHID + col] = W2[j];
    }
}

// ---------------- A split: fp32 -> bf16 hi/lo ----------------
__global__ void k_split_a(const float* __restrict__ X, __nv_bfloat16* __restrict__ hi,
                          __nv_bfloat16* __restrict__ lo, int n2) {
    int i = blockIdx.x * blockDim.x + threadIdx.x;
    if (i >= n2) return;
    float2 v = ((const float2*)X)[i];
    uint32_t hp, lp;
    split2(v.x, v.y, hp, lp);
    ((uint32_t*)hi)[i] = hp;
    ((uint32_t*)lo)[i] = lp;
}

// ---------------- (acc/den) -> elu -> split  (for h3; per-node denominator) ----------------
__global__ void k_elu_split(const float* __restrict__ X, __nv_bfloat16* __restrict__ hi,
                            __nv_bfloat16* __restrict__ lo, int n2) {
    int i = blockIdx.x * blockDim.x + threadIdx.x;
    if (i >= n2) return;
    int node = i / (DHID / 2);
    float dn = g_den[node];
    float w = dn > 0.f ? __fdividef(1.f, dn) : 0.f;
    float2 v = ((const float2*)X)[i];
    v.x *= w; v.y *= w;
    v.x = v.x > 0.f ? v.x : expm1f(v.x);
    v.y = v.y > 0.f ? v.y : expm1f(v.y);
    uint32_t hp, lp;
    split2(v.x, v.y, hp, lp);
    ((uint32_t*)hi)[i] = hp;
    ((uint32_t*)lo)[i] = lp;
}

// ---------------- init ----------------
__global__ void k_init() {
    size_t i = blockIdx.x * (size_t)blockDim.x + threadIdx.x;
    size_t stride = (size_t)gridDim.x * blockDim.x;
    float4 z = make_float4(0.f, 0.f, 0.f, 0.f);
    float4* a1 = (float4*)g_buf1;
    const size_t n4 = (size_t)N_NODES * DHID / 4;
    for (size_t j = i; j < n4; j += stride) a1[j] = z;
    for (size_t j = i; j < N_NODES; j += stride) { g_den[j] = 0.f; g_mx[j] = 0u; }
}

// ---------------- edge scores ----------------
__global__ __launch_bounds__(256) void k_edge_score(const int* __restrict__ src,
                                                    const int* __restrict__ dst,
                                                    const float* __restrict__ h,
                                                    const float* __restrict__ att) {
    int e = (int)((blockIdx.x * (size_t)blockDim.x + threadIdx.x) >> 5);
    int lane = threadIdx.x & 31;
    if (e >= N_EDGES) return;
    int s = src[e], d = dst[e];
    const float4* hs = (const float4*)(h + (size_t)s * DHID);
    const float4* hd = (const float4*)(h + (size_t)d * DHID);
    const float4* at = (const float4*)att;
    float sum = 0.f;
#pragma unroll
    for (int i = 0; i < 4; i++) {
        int idx = lane + i * 32;
        float4 a = hs[idx], b = hd[idx], t = __ldg(&at[idx]);
        float x;
        x = a.x + b.x; sum += t.x * (x > 0.f ? x : NEG_SLOPE * x);
        x = a.y + b.y; sum += t.y * (x > 0.f ? x : NEG_SLOPE * x);
        x = a.z + b.z; sum += t.z * (x > 0.f ? x : NEG_SLOPE * x);
        x = a.w + b.w; sum += t.w * (x > 0.f ? x : NEG_SLOPE * x);
    }
#pragma unroll
    for (int o = 16; o > 0; o >>= 1) sum += __shfl_xor_sync(0xffffffffu, sum, o);
    if (lane == 0) {
        g_escore[e] = sum;
        unsigned enc = __float_as_uint(sum);
        enc = (enc & 0x80000000u) ? ~enc : (enc | 0x80000000u);
        atomicMax(&g_mx[d], enc);
    }
}

// ---------------- scatter aggregation: Acc[dst] += w * X[src], w = exp(e - max[dst]) ----------------
template <bool FIRST>
__global__ __launch_bounds__(256) void k_aggregate(const int* __restrict__ src,
                                                   const int* __restrict__ dst,
                                                   const float* __restrict__ X,
                                                   float* __restrict__ Acc) {
    int e = (int)((blockIdx.x * (size_t)blockDim.x + threadIdx.x) >> 5);
    int lane = threadIdx.x & 31;
    if (e >= N_EDGES) return;
    int s = src[e], d = dst[e];
    float w;
    if (FIRST) {
        if (lane == 0) {
            unsigned u = g_mx[d];
            unsigned b = (u & 0x80000000u) ? (u & 0x7FFFFFFFu) : ~u;
            float m = __uint_as_float(b);
            w = __expf(g_escore[e] - m);
            g_ex[e] = w;
            atomicAdd(&g_den[d], w);
        }
        w = __shfl_sync(0xffffffffu, w, 0);
    } else {
        w = g_ex[e];
    }
    const float4* xs = (const float4*)(X + (size_t)s * DHID);
    float* out = Acc + (size_t)d * DHID;
#pragma unroll
    for (int i = 0; i < 4; i++) {
        int idx = lane + i * 32;
        float4 v = xs[idx];
        float* p = out + idx * 4;
        asm volatile("red.global.add.v4.f32 [%0], {%1, %2, %3, %4};"
                     :: "l"(p), "f"(w * v.x), "f"(w * v.y), "f"(w * v.z), "f"(w * v.w)
                     : "memory");
    }
}

// ---------------- h2 = elu(acc1/den) @ W2, then re-zero acc1 rows ----------------
__global__ __launch_bounds__(256) void k_h2(float* __restrict__ acc1,
                                            const float* __restrict__ W2,
                                            float* __restrict__ out) {
    __shared__ float hs[8][DHID];
    const int tid = threadIdx.x;
    const int rowBase = blockIdx.x * 8;
    float4* srcp = (float4*)(acc1 + (size_t)rowBase * DHID);
    float4* dstp = (float4*)hs;
    for (int i = tid; i < 8 * DHID / 4; i += 256) {
        int node = rowBase + i / (DHID / 4);
        float dn = g_den[node];
        float w = dn > 0.f ? __fdividef(1.f, dn) : 0.f;
        float4 v = srcp[i];
        v.x *= w; v.y *= w; v.z *= w; v.w *= w;
        v.x = v.x > 0.f ? v.x : expm1f(v.x);
        v.y = v.y > 0.f ? v.y : expm1f(v.y);
        v.z = v.z > 0.f ? v.z : expm1f(v.z);
        v.w = v.w > 0.f ? v.w : expm1f(v.w);
        dstp[i] = v;
    }
    __syncthreads();
    int r = tid >> 5;
    int c = tid & 31;
    if (c < DOUT) {
        float acc = 0.f;
#pragma unroll 8
        for (int k = 0; k < DHID; k++) acc += hs[r][k] * __ldg(&W2[k * DOUT + c]);
        out[(size_t)(rowBase + r) * DOUT + c] = acc;
    }
    // re-zero these acc1 rows for the second aggregation
    float4 z = make_float4(0.f, 0.f, 0.f, 0.f);
    for (int i = tid; i < 8 * DHID / 4; i += 256) srcp[i] = z;
}

// ---------------- g = h2 @ W2^T ----------------
__global__ __launch_bounds__(256) void k_g(const float* __restrict__ h2,
                                           float* __restrict__ gout) {
    __shared__ float hr[DOUT];
    int row = blockIdx.y;
    int col = blockIdx.x * 256 + threadIdx.x;
    if (threadIdx.x < DOUT) hr[threadIdx.x] = __ldg(&h2[(size_t)row * DOUT + threadIdx.x]);
    __syncthreads();
    float acc = 0.f;
#pragma unroll
    for (int k = 0; k < DOUT; k++) acc += hr[k] * g_w2t[k * DHID + col];
    gout[(size_t)row * DHID + col] = acc;
}

// ---------------- launch ----------------
extern "C" void kernel_launch(void* const* d_in, const int* in_sizes, int n_in,
                              void* d_out, int out_size) {
    const float* features = (const float*)d_in[0];
    const int*   eidx     = (const int*)d_in[1];
    const float* W1       = (const float*)d_in[2];
    const float* att1     = (const float*)d_in[3];
    const float* W2       = (const float*)d_in[4];
    const float* W4       = (const float*)d_in[5];
    float* out = (float*)d_out;
    const int* src = eidx;
    const int* dst = eidx + N_EDGES;

    float *p_buf0, *p_buf1;
    __nv_bfloat16 *p_w1h, *p_w1l, *p_w4h, *p_w4l, *p_ah, *p_al;
    cudaGetSymbolAddress((void**)&p_buf0, g_buf0);
    cudaGetSymbolAddress((void**)&p_buf1, g_buf1);
    cudaGetSymbolAddress((void**)&p_w1h, g_w1t_hi);
    cudaGetSymbolAddress((void**)&p_w1l, g_w1t_lo);
    cudaGetSymbolAddress((void**)&p_w4h, g_w4t_hi);
    cudaGetSymbolAddress((void**)&p_w4l, g_w4t_lo);
    cudaGetSymbolAddress((void**)&p_ah, g_a_hi);
    cudaGetSymbolAddress((void**)&p_al, g_a_lo);

    cudaFuncSetAttribute(k_mma_gemm, cudaFuncAttributeMaxDynamicSharedMemorySize, 2 * STG_BYTES);

    float* out_h2 = out;                          // [50000, 30]
    float* out_h4 = out + (size_t)N_NODES * DOUT; // [50000, 1024]

    const int edgeBlocks = (N_EDGES * 32 + 255) / 256;
    const int mtiles = (N_NODES + 127) / 128;     // 391

    // 1) zero acc + softmax stats
    k_init<<<2048, 256>>>();
    // 2) all weight prep (one launch)
    k_prep_all<<<(PREP_W1 + PREP_W4 + PREP_W2 + 255) / 256, 256>>>(W1, W4, W2);
    // 3) split features -> a_hi/a_lo
    k_split_a<<<(N_NODES * DIN / 2 + 255) / 256, 256>>>(features, p_ah, p_al, N_NODES * DIN / 2);
    // 4) h = X @ W1 -> buf0  (tensor cores; launch #4 -> ncu-profiled)
    {
        dim3 grid(DHID / 128, mtiles);
        k_mma_gemm<<<grid, 256, 2 * STG_BYTES>>>(p_ah, p_al, p_w1h, p_w1l, p_buf0, N_NODES, DIN, DHID);
    }
    // 5) edge scores + segment max
    k_edge_score<<<edgeBlocks, 256>>>(src, dst, p_buf0, att1);
    // 6) agg1: buf1[dst] += ex * h[src]; accumulates den; stores ex
    k_aggregate<true><<<edgeBlocks, 256>>>(src, dst, p_buf0, p_buf1);
    // 7) h2 = elu(buf1/den) @ W2 -> out; re-zeros buf1
    k_h2<<<N_NODES / 8, 256>>>(p_buf1, W2, out_h2);
    // 8) g = h2 @ W2^T -> buf0
    {
        dim3 grid(DHID / 256, N_NODES);
        k_g<<<grid, 256>>>(out_h2, p_buf0);
    }
    // 9) agg2: buf1[dst] += ex * g[src]
    k_aggregate<false><<<edgeBlocks, 256>>>(src, dst, p_buf0, p_buf1);
    // 10) h3 = elu(buf1/den) fused with bf16 split -> a_hi/a_lo (K=512 layout)
    k_elu_split<<<(N_NODES * DHID / 2 + 255) / 256, 256>>>(p_buf1, p_ah, p_al, N_NODES * DHID / 2);
    // 11) h4 = h3 @ W4 -> out  (tensor cores)
    {
        dim3 grid(DIN / 128, mtiles);
        k_mma_gemm<<<grid, 256, 2 * STG_BYTES>>>(p_ah, p_al, p_w4h, p_w4l, out_h4, N_NODES, DHID, DIN);
    }
}

// round 13
// speedup vs baseline: 1.5426x; 1.0747x over previous
#include <cuda_runtime.h>
#include <cuda_bf16.h>
#include <cstdint>

#define N_NODES 50000
#define PAD_M   50048
#define N_EDGES 300000
#define DIN     1024
#define DHID    512
#define DOUT    30
#define NEG_SLOPE 0.2f

// ---------------- scratch (static device globals) ----------------
__device__ __align__(16) float g_buf0[N_NODES * DHID];   // h, then g
__device__ __align__(16) float g_buf1[N_NODES * DHID];   // h1_norm, then h3_norm
__device__ float g_se[N_EDGES];          // edge scores, CSR(slot) order
__device__ int   g_deg[N_NODES];
__device__ int   g_off[N_NODES + 1];
__device__ int   g_cur[N_NODES];
__device__ int   g_esrc[N_EDGES];        // src node per slot
__device__ int   g_slot[N_EDGES];        // edge -> slot map
__device__ __align__(16) float g_w2t[DOUT * DHID];
// pre-transposed + bf16-split weights: [N][K] layout
__device__ __align__(16) __nv_bfloat16 g_w1t_hi[DHID * DIN];
__device__ __align__(16) __nv_bfloat16 g_w1t_lo[DHID * DIN];
__device__ __align__(16) __nv_bfloat16 g_w4t_hi[DIN * DHID];
__device__ __align__(16) __nv_bfloat16 g_w4t_lo[DIN * DHID];
// A-operand bf16 split (reused: features K=1024, then h3 K=512)
__device__ __align__(16) __nv_bfloat16 g_a_hi[(size_t)PAD_M * DIN];
__device__ __align__(16) __nv_bfloat16 g_a_lo[(size_t)PAD_M * DIN];

// ================= helpers =================
__device__ __forceinline__ uint32_t smem_u32(const void* p) {
    uint32_t a;
    asm("{ .reg .u64 t; cvta.to.shared.u64 t, %1; cvt.u32.u64 %0, t; }" : "=r"(a) : "l"(p));
    return a;
}
#define CP_ASYNC16(dst, src) asm volatile("cp.async.cg.shared.global [%0], [%1], 16;" :: "r"(dst), "l"(src) : "memory")
#define CP_COMMIT()          asm volatile("cp.async.commit_group;" ::: "memory")
#define CP_WAIT1()           asm volatile("cp.async.wait_group 1;" ::: "memory")
#define CP_WAIT0()           asm volatile("cp.async.wait_group 0;" ::: "memory")

__device__ __forceinline__ void ldsm_x4(uint32_t& r0, uint32_t& r1, uint32_t& r2, uint32_t& r3, uint32_t a) {
    asm volatile("ldmatrix.sync.aligned.m8n8.x4.shared.b16 {%0,%1,%2,%3}, [%4];"
                 : "=r"(r0), "=r"(r1), "=r"(r2), "=r"(r3) : "r"(a));
}
__device__ __forceinline__ void mma16816(float* c, const uint32_t* a, const uint32_t* b) {
    asm volatile("mma.sync.aligned.m16n8k16.row.col.f32.bf16.bf16.f32 "
                 "{%0,%1,%2,%3}, {%4,%5,%6,%7}, {%8,%9}, {%0,%1,%2,%3};"
                 : "+f"(c[0]), "+f"(c[1]), "+f"(c[2]), "+f"(c[3])
                 : "r"(a[0]), "r"(a[1]), "r"(a[2]), "r"(a[3]), "r"(b[0]), "r"(b[1]));
}
__device__ __forceinline__ void split2(float x, float y, uint32_t& hi, uint32_t& lo) {
    __nv_bfloat16 hx = __float2bfloat16(x);
    __nv_bfloat16 hy = __float2bfloat16(y);
    __nv_bfloat16 lx = __float2bfloat16(x - __bfloat162float(hx));
    __nv_bfloat16 ly = __float2bfloat16(y - __bfloat162float(hy));
    hi = ((uint32_t)__bfloat16_as_ushort(hy) << 16) | (uint32_t)__bfloat16_as_ushort(hx);
    lo = ((uint32_t)__bfloat16_as_ushort(ly) << 16) | (uint32_t)__bfloat16_as_ushort(lx);
}

// ================= bf16-split tensor-core GEMM (R10 structure, unchanged) =================
#define SROWB   80
#define MATB    (128 * SROWB)       // 10240
#define STG_BYTES (4 * MATB)        // 40960

#define LOAD_STAGE(bufbase, k0)                                                       \
    _Pragma("unroll")                                                                 \
    for (int q = 0; q < 8; q++) {                                                     \
        int c = tid + q * 256;                                                        \
        int mat = c >> 9, row = (c >> 2) & 127, cc = c & 3;                           \
        uint32_t dstp = (bufbase) + mat * MATB + row * SROWB + cc * 16;               \
        const __nv_bfloat16* srcp;                                                    \
        if (mat == 0)      srcp = Ahi + (size_t)(mtile * 128 + row) * K + (k0) + cc * 8; \
        else if (mat == 1) srcp = Alo + (size_t)(mtile * 128 + row) * K + (k0) + cc * 8; \
        else if (mat == 2) srcp = Bhi + (size_t)(ntile * 128 + row) * K + (k0) + cc * 8; \
        else               srcp = Blo + (size_t)(ntile * 128 + row) * K + (k0) + cc * 8; \
        CP_ASYNC16(dstp, srcp);                                                       \
    }

__global__ __launch_bounds__(256, 2) void k_mma_gemm(const __nv_bfloat16* __restrict__ Ahi,
                                                     const __nv_bfloat16* __restrict__ Alo,
                                                     const __nv_bfloat16* __restrict__ Bhi,
                                                     const __nv_bfloat16* __restrict__ Blo,
                                                     float* __restrict__ C,
                                                     int M, int K, int N) {
    extern __shared__ char smem[];
    const int tid = threadIdx.x;
    const int lane = tid & 31, wid = tid >> 5;
    const int wm = (wid & 1) * 64, wn = (wid >> 1) * 32;
    const int mtile = blockIdx.y, ntile = blockIdx.x;
    const int nstages = K >> 5;
    const uint32_t sb = smem_u32(smem);

    float acc[4][4][4];
#pragma unroll
    for (int i = 0; i < 4; i++)
#pragma unroll
        for (int j = 0; j < 4; j++)
#pragma unroll
            for (int t = 0; t < 4; t++) acc[i][j][t] = 0.f;

    LOAD_STAGE(sb, 0);
    CP_COMMIT();

    const int ar = lane & 15, ac = (lane >> 4) * 8;
    const int bnr = ((lane >> 4) * 8) + (lane & 7);
    const int bkc = ((lane >> 3) & 1) * 8;

    for (int s = 0; s < nstages; s++) {
        if (s + 1 < nstages) {
            LOAD_STAGE(sb + (uint32_t)(((s + 1) & 1) * STG_BYTES), (s + 1) * 32);
            CP_COMMIT();
            CP_WAIT1();
        } else {
            CP_WAIT0();
        }
        __syncthreads();
        const uint32_t st = sb + (uint32_t)((s & 1) * STG_BYTES);
#pragma unroll
        for (int ks = 0; ks < 2; ks++) {
            uint32_t bh[4][2], bl[4][2];
#pragma unroll
            for (int jp = 0; jp < 2; jp++) {
                uint32_t baddr = st + 2u * MATB +
                    (uint32_t)((wn + jp * 16 + bnr) * SROWB + (ks * 16 + bkc) * 2);
                ldsm_x4(bh[jp * 2][0], bh[jp * 2][1], bh[jp * 2 + 1][0], bh[jp * 2 + 1][1], baddr);
                ldsm_x4(bl[jp * 2][0], bl[jp * 2][1], bl[jp * 2 + 1][0], bl[jp * 2 + 1][1], baddr + MATB);
            }
#pragma unroll
            for (int i = 0; i < 4; i++) {
                uint32_t ah[4], al[4];
                uint32_t aaddr = st + (uint32_t)((wm + i * 16 + ar) * SROWB + (ks * 16 + ac) * 2);
                ldsm_x4(ah[0], ah[1], ah[2], ah[3], aaddr);
                ldsm_x4(al[0], al[1], al[2], al[3], aaddr + MATB);
#pragma unroll
                for (int j = 0; j < 4; j++) {
                    mma16816(acc[i][j], ah, bh[j]);
                    mma16816(acc[i][j], ah, bl[j]);
                    mma16816(acc[i][j], al, bh[j]);
                }
            }
        }
        __syncthreads();
    }
    const int r0 = lane >> 2, cq = (lane & 3) * 2;
#pragma unroll
    for (int i = 0; i < 4; i++) {
#pragma unroll
        for (int j = 0; j < 4; j++) {
            int gr = mtile * 128 + wm + i * 16 + r0;
            int gc = ntile * 128 + wn + j * 8 + cq;
            if (gr < M) *(float2*)&C[(size_t)gr * N + gc] = make_float2(acc[i][j][0], acc[i][j][1]);
            if (gr + 8 < M) *(float2*)&C[(size_t)(gr + 8) * N + gc] = make_float2(acc[i][j][2], acc[i][j][3]);
        }
    }
}

// ---------------- fused weight prep ----------------
#define PREP_W1 (DIN * DHID)
#define PREP_W4 (DHID * DIN)
#define PREP_W2 (DHID * DOUT)
__global__ void k_prep_all(const float* __restrict__ W1, const float* __restrict__ W4,
                           const float* __restrict__ W2) {
    int i = blockIdx.x * blockDim.x + threadIdx.x;
    if (i < PREP_W1) {
        int k = i / DHID, n = i % DHID;
        float x = W1[i];
        __nv_bfloat16 h = __float2bfloat16(x);
        g_w1t_hi[(size_t)n * DIN + k] = h;
        g_w1t_lo[(size_t)n * DIN + k] = __float2bfloat16(x - __bfloat162float(h));
    } else if (i < PREP_W1 + PREP_W4) {
        int j = i - PREP_W1;
        int k = j / DIN, n = j % DIN;
        float x = W4[j];
        __nv_bfloat16 h = __float2bfloat16(x);
        g_w4t_hi[(size_t)n * DHID + k] = h;
        g_w4t_lo[(size_t)n * DHID + k] = __float2bfloat16(x - __bfloat162float(h));
    } else if (i < PREP_W1 + PREP_W4 + PREP_W2) {
        int j = i - PREP_W1 - PREP_W4;
        int col = j / DOUT, k = j % DOUT;
        g_w2t[k * DHID + col] = W2[j];
    }
}

// ---------------- A split: fp32 -> bf16 hi/lo ----------------
__global__ void k_split_a(const float* __restrict__ X, __nv_bfloat16* __restrict__ hi,
                          __nv_bfloat16* __restrict__ lo, int n2) {
    int i = blockIdx.x * blockDim.x + threadIdx.x;
    if (i >= n2) return;
    float2 v = ((const float2*)X)[i];
    uint32_t hp, lp;
    split2(v.x, v.y, hp, lp);
    ((uint32_t*)hi)[i] = hp;
    ((uint32_t*)lo)[i] = lp;
}

// ---------------- elu -> split (h3 is already normalized) ----------------
__global__ void k_elu_split(const float* __restrict__ X, __nv_bfloat16* __restrict__ hi,
                            __nv_bfloat16* __restrict__ lo, int n2) {
    int i = blockIdx.x * blockDim.x + threadIdx.x;
    if (i >= n2) return;
    float2 v = ((const float2*)X)[i];
    v.x = v.x > 0.f ? v.x : expm1f(v.x);
    v.y = v.y > 0.f ? v.y : expm1f(v.y);
    uint32_t hp, lp;
    split2(v.x, v.y, hp, lp);
    ((uint32_t*)hi)[i] = hp;
    ((uint32_t*)lo)[i] = lp;
}

// ---------------- CSR build ----------------
__global__ void k_zero_deg() {
    int i = blockIdx.x * blockDim.x + threadIdx.x;
    if (i < N_NODES) g_deg[i] = 0;
}
__global__ void k_deg(const int* __restrict__ dst) {
    int e = blockIdx.x * blockDim.x + threadIdx.x;
    if (e < N_EDGES) atomicAdd(&g_deg[dst[e]], 1);
}
#define SCAN_T 1024
#define SCAN_CHUNK ((N_NODES + SCAN_T - 1) / SCAN_T)   // 49
__global__ __launch_bounds__(SCAN_T) void k_scan() {
    __shared__ int ps[SCAN_T];
    int t = threadIdx.x;
    int b0 = t * SCAN_CHUNK;
    int b1 = min(b0 + SCAN_CHUNK, N_NODES);
    int s = 0;
    for (int n = b0; n < b1; n++) s += g_deg[n];
    ps[t] = s;
    __syncthreads();
    for (int off = 1; off < SCAN_T; off <<= 1) {
        int v = ps[t];
        int add = (t >= off) ? ps[t - off] : 0;
        __syncthreads();
        ps[t] = v + add;
        __syncthreads();
    }
    int run = (t > 0) ? ps[t - 1] : 0;
    for (int n = b0; n < b1; n++) {
        g_off[n] = run;
        g_cur[n] = run;
        run += g_deg[n];
    }
    if (t == SCAN_T - 1) g_off[N_NODES] = run;
}
__global__ void k_fill(const int* __restrict__ src, const int* __restrict__ dst) {
    int e = blockIdx.x * blockDim.x + threadIdx.x;
    if (e >= N_EDGES) return;
    int slot = atomicAdd(&g_cur[dst[e]], 1);
    g_esrc[slot] = src[e];
    g_slot[e] = slot;
}

// ---------------- edge scores -> g_se[slot] ----------------
__global__ __launch_bounds__(256) void k_edge_score(const int* __restrict__ src,
                                                    const int* __restrict__ dst,
                                                    const float* __restrict__ h,
                                                    const float* __restrict__ att) {
    int e = (int)((blockIdx.x * (size_t)blockDim.x + threadIdx.x) >> 5);
    int lane = threadIdx.x & 31;
    if (e >= N_EDGES) return;
    int s = src[e], d = dst[e];
    const float4* hs = (const float4*)(h + (size_t)s * DHID);
    const float4* hd = (const float4*)(h + (size_t)d * DHID);
    const float4* at = (const float4*)att;
    float sum = 0.f;
#pragma unroll
    for (int i = 0; i < 4; i++) {
        int idx = lane + i * 32;
        float4 a = hs[idx], b = hd[idx], t = __ldg(&at[idx]);
        float x;
        x = a.x + b.x; sum += t.x * (x > 0.f ? x : NEG_SLOPE * x);
        x = a.y + b.y; sum += t.y * (x > 0.f ? x : NEG_SLOPE * x);
        x = a.z + b.z; sum += t.z * (x > 0.f ? x : NEG_SLOPE * x);
        x = a.w + b.w; sum += t.w * (x > 0.f ? x : NEG_SLOPE * x);
    }
#pragma unroll
    for (int o = 16; o > 0; o >>= 1) sum += __shfl_xor_sync(0xffffffffu, sum, o);
    if (lane == 0) g_se[g_slot[e]] = sum;
}

// ---------------- CSR gather-aggregation: Out[n] = (sum_j w_j X[src_j]) / den, softmax local ----------------
__global__ __launch_bounds__(256) void k_agg_csr(const float* __restrict__ X,
                                                 float* __restrict__ Out) {
    int node = (int)((blockIdx.x * (size_t)blockDim.x + threadIdx.x) >> 5);
    int lane = threadIdx.x & 31;
    if (node >= N_NODES) return;
    int off0 = g_off[node], off1 = g_off[node + 1];
    float4 a0 = make_float4(0.f, 0.f, 0.f, 0.f), a1 = a0, a2 = a0, a3 = a0;
    if (off1 > off0) {
        // local softmax stats (deterministic warp reductions)
        float m = __int_as_float(0xff800000);          // -inf
        for (int j = off0 + lane; j < off1; j += 32) m = fmaxf(m, g_se[j]);
#pragma unroll
        for (int o = 16; o > 0; o >>= 1) m = fmaxf(m, __shfl_xor_sync(0xffffffffu, m, o));
        float ds = 0.f;
        for (int j = off0 + lane; j < off1; j += 32) ds += __expf(g_se[j] - m);
#pragma unroll
        for (int o = 16; o > 0; o >>= 1) ds += __shfl_xor_sync(0xffffffffu, ds, o);
        float inv = __fdividef(1.f, ds);
        // gather rows
        for (int j = off0; j < off1; j++) {
            float w = __expf(g_se[j] - m);             // uniform across lanes
            const float4* row = (const float4*)(X + (size_t)g_esrc[j] * DHID);
            float4 v;
            v = row[lane];       a0.x += w * v.x; a0.y += w * v.y; a0.z += w * v.z; a0.w += w * v.w;
            v = row[lane + 32];  a1.x += w * v.x; a1.y += w * v.y; a1.z += w * v.z; a1.w += w * v.w;
            v = row[lane + 64];  a2.x += w * v.x; a2.y += w * v.y; a2.z += w * v.z; a2.w += w * v.w;
            v = row[lane + 96];  a3.x += w * v.x; a3.y += w * v.y; a3.z += w * v.z; a3.w += w * v.w;
        }
        a0.x *= inv; a0.y *= inv; a0.z *= inv; a0.w *= inv;
        a1.x *= inv; a1.y *= inv; a1.z *= inv; a1.w *= inv;
        a2.x *= inv; a2.y *= inv; a2.z *= inv; a2.w *= inv;
        a3.x *= inv; a3.y *= inv; a3.z *= inv; a3.w *= inv;
    }
    float4* o = (float4*)(Out + (size_t)node * DHID);
    o[lane] = a0;
    o[lane + 32] = a1;
    o[lane + 64] = a2;
    o[lane + 96] = a3;
}

// ---------------- h2 = elu(h1_norm) @ W2 ----------------
__global__ __launch_bounds__(256) void k_h2(const float* __restrict__ h1,
                                            const float* __restrict__ W2,
                                            float* __restrict__ out) {
    __shared__ float hs[8][DHID];
    const int tid = threadIdx.x;
    const int rowBase = blockIdx.x * 8;
    const float4* srcp = (const float4*)(h1 + (size_t)rowBase * DHID);
    float4* dstp = (float4*)hs;
    for (int i = tid; i < 8 * DHID / 4; i += 256) {
        float4 v = srcp[i];
        v.x = v.x > 0.f ? v.x : expm1f(v.x);
        v.y = v.y > 0.f ? v.y : expm1f(v.y);
        v.z = v.z > 0.f ? v.z : expm1f(v.z);
        v.w = v.w > 0.f ? v.w : expm1f(v.w);
        dstp[i] = v;
    }
    __syncthreads();
    int r = tid >> 5;
    int c = tid & 31;
    if (c < DOUT) {
        float acc = 0.f;
#pragma unroll 8
        for (int k = 0; k < DHID; k++) acc += hs[r][k] * __ldg(&W2[k * DOUT + c]);
        out[(size_t)(rowBase + r) * DOUT + c] = acc;
    }
}

// ---------------- g = h2 @ W2^T ----------------
__global__ __launch_bounds__(256) void k_g(const float* __restrict__ h2,
                                           float* __restrict__ gout) {
    __shared__ float hr[DOUT];
    int row = blockIdx.y;
    int col = blockIdx.x * 256 + threadIdx.x;
    if (threadIdx.x < DOUT) hr[threadIdx.x] = __ldg(&h2[(size_t)row * DOUT + threadIdx.x]);
    __syncthreads();
    float acc = 0.f;
#pragma unroll
    for (int k = 0; k < DOUT; k++) acc += hr[k] * g_w2t[k * DHID + col];
    gout[(size_t)row * DHID + col] = acc;
}

// ---------------- launch ----------------
extern "C" void kernel_launch(void* const* d_in, const int* in_sizes, int n_in,
                              void* d_out, int out_size) {
    const float* features = (const float*)d_in[0];
    const int*   eidx     = (const int*)d_in[1];
    const float* W1       = (const float*)d_in[2];
    const float* att1     = (const float*)d_in[3];
    const float* W2       = (const float*)d_in[4];
    const float* W4       = (const float*)d_in[5];
    float* out = (float*)d_out;
    const int* src = eidx;
    const int* dst = eidx + N_EDGES;

    float *p_buf0, *p_buf1;
    __nv_bfloat16 *p_w1h, *p_w1l, *p_w4h, *p_w4l, *p_ah, *p_al;
    cudaGetSymbolAddress((void**)&p_buf0, g_buf0);
    cudaGetSymbolAddress((void**)&p_buf1, g_buf1);
    cudaGetSymbolAddress((void**)&p_w1h, g_w1t_hi);
    cudaGetSymbolAddress((void**)&p_w1l, g_w1t_lo);
    cudaGetSymbolAddress((void**)&p_w4h, g_w4t_hi);
    cudaGetSymbolAddress((void**)&p_w4l, g_w4t_lo);
    cudaGetSymbolAddress((void**)&p_ah, g_a_hi);
    cudaGetSymbolAddress((void**)&p_al, g_a_lo);

    cudaFuncSetAttribute(k_mma_gemm, cudaFuncAttributeMaxDynamicSharedMemorySize, 2 * STG_BYTES);

    float* out_h2 = out;                          // [50000, 30]
    float* out_h4 = out + (size_t)N_NODES * DOUT; // [50000, 1024]

    const int edgeBlocks = (N_EDGES * 32 + 255) / 256;
    const int nodeWarpBlocks = (N_NODES * 32 + 255) / 256;
    const int mtiles = (N_NODES + 127) / 128;     // 391

    // 1) zero degree counters
    k_zero_deg<<<(N_NODES + 255) / 256, 256>>>();
    // 2) all weight prep
    k_prep_all<<<(PREP_W1 + PREP_W4 + PREP_W2 + 255) / 256, 256>>>(W1, W4, W2);
    // 3) split features -> a_hi/a_lo
    k_split_a<<<(N_NODES * DIN / 2 + 255) / 256, 256>>>(features, p_ah, p_al, N_NODES * DIN / 2);
    // 4) h = X @ W1 -> buf0  (tensor cores; launch #4 -> ncu-profiled)
    {
        dim3 grid(DHID / 128, mtiles);
        k_mma_gemm<<<grid, 256, 2 * STG_BYTES>>>(p_ah, p_al, p_w1h, p_w1l, p_buf0, N_NODES, DIN, DHID);
    }
    // 5-7) CSR build: degree histogram, offsets scan, slot fill
    k_deg<<<(N_EDGES + 255) / 256, 256>>>(dst);
    k_scan<<<1, SCAN_T>>>();
    k_fill<<<(N_EDGES + 255) / 256, 256>>>(src, dst);
    // 8) edge scores -> g_se[slot]
    k_edge_score<<<edgeBlocks, 256>>>(src, dst, p_buf0, att1);
    // 9) agg1 (CSR gather): buf1 = softmax-weighted mean of h rows
    k_agg_csr<<<nodeWarpBlocks, 256>>>(p_buf0, p_buf1);
    // 10) h2 = elu(buf1) @ W2 -> out
    k_h2<<<N_NODES / 8, 256>>>(p_buf1, W2, out_h2);
    // 11) g = h2 @ W2^T -> buf0
    {
        dim3 grid(DHID / 256, N_NODES);
        k_g<<<grid, 256>>>(out_h2, p_buf0);
    }
    // 12) agg2 (CSR gather): buf1 = softmax-weighted mean of g rows
    k_agg_csr<<<nodeWarpBlocks, 256>>>(p_buf0, p_buf1);
    // 13) h3 = elu(buf1) fused with bf16 split -> a_hi/a_lo (K=512 layout)
    k_elu_split<<<(N_NODES * DHID / 2 + 255) / 256, 256>>>(p_buf1, p_ah, p_al, N_NODES * DHID / 2);
    // 14) h4 = h3 @ W4 -> out
    {
        dim3 grid(DIN / 128, mtiles);
        k_mma_gemm<<<grid, 256, 2 * STG_BYTES>>>(p_ah, p_al, p_w4h, p_w4l, out_h4, N_NODES, DHID, DIN);
    }
}

// round 15
// speedup vs baseline: 1.6819x; 1.0903x over previous
#include <cuda_runtime.h>
#include <cuda_bf16.h>
#include <cstdint>

#define N_NODES 50000
#define PAD_M   50048
#define N_EDGES 300000
#define DIN     1024
#define DHID    512
#define DOUT    30
#define NEG_SLOPE 0.2f

// ---------------- scratch (static device globals) ----------------
__device__ __align__(16) float g_buf0[N_NODES * DHID];   // h
__device__ __align__(16) float g_buf1[N_NODES * DHID];   // h1_norm
__device__ float g_se[N_EDGES];          // edge scores, CSR(slot) order
__device__ int   g_deg[N_NODES];
__device__ int   g_off[N_NODES + 1];
__device__ int   g_cur[N_NODES];
__device__ int   g_esrc[N_EDGES];        // src node per slot
__device__ int   g_slot[N_EDGES];        // edge -> slot map
__device__ __align__(16) float g_h2agg[N_NODES * 32];    // aggregated h2 (padded 30->32)
__device__ __align__(16) float g_w2t[DOUT * DHID];
// pre-transposed + bf16-split weights: [N][K] layout
__device__ __align__(16) __nv_bfloat16 g_w1t_hi[DHID * DIN];
__device__ __align__(16) __nv_bfloat16 g_w1t_lo[DHID * DIN];
__device__ __align__(16) __nv_bfloat16 g_w4t_hi[DIN * DHID];
__device__ __align__(16) __nv_bfloat16 g_w4t_lo[DIN * DHID];
// A-operand bf16 split (reused: features K=1024, then h3 K=512)
__device__ __align__(16) __nv_bfloat16 g_a_hi[(size_t)PAD_M * DIN];
__device__ __align__(16) __nv_bfloat16 g_a_lo[(size_t)PAD_M * DIN];

// ================= helpers =================
__device__ __forceinline__ uint32_t smem_u32(const void* p) {
    uint32_t a;
    asm("{ .reg .u64 t; cvta.to.shared.u64 t, %1; cvt.u32.u64 %0, t; }" : "=r"(a) : "l"(p));
    return a;
}
#define CP_ASYNC16(dst, src) asm volatile("cp.async.cg.shared.global [%0], [%1], 16;" :: "r"(dst), "l"(src) : "memory")
#define CP_COMMIT()          asm volatile("cp.async.commit_group;" ::: "memory")
#define CP_WAIT1()           asm volatile("cp.async.wait_group 1;" ::: "memory")
#define CP_WAIT0()           asm volatile("cp.async.wait_group 0;" ::: "memory")

__device__ __forceinline__ void ldsm_x4(uint32_t& r0, uint32_t& r1, uint32_t& r2, uint32_t& r3, uint32_t a) {
    asm volatile("ldmatrix.sync.aligned.m8n8.x4.shared.b16 {%0,%1,%2,%3}, [%4];"
                 : "=r"(r0), "=r"(r1), "=r"(r2), "=r"(r3) : "r"(a));
}
__device__ __forceinline__ void mma16816(float* c, const uint32_t* a, const uint32_t* b) {
    asm volatile("mma.sync.aligned.m16n8k16.row.col.f32.bf16.bf16.f32 "
                 "{%0,%1,%2,%3}, {%4,%5,%6,%7}, {%8,%9}, {%0,%1,%2,%3};"
                 : "+f"(c[0]), "+f"(c[1]), "+f"(c[2]), "+f"(c[3])
                 : "r"(a[0]), "r"(a[1]), "r"(a[2]), "r"(a[3]), "r"(b[0]), "r"(b[1]));
}
__device__ __forceinline__ void split2(float x, float y, uint32_t& hi, uint32_t& lo) {
    __nv_bfloat16 hx = __float2bfloat16(x);
    __nv_bfloat16 hy = __float2bfloat16(y);
    __nv_bfloat16 lx = __float2bfloat16(x - __bfloat162float(hx));
    __nv_bfloat16 ly = __float2bfloat16(y - __bfloat162float(hy));
    hi = ((uint32_t)__bfloat16_as_ushort(hy) << 16) | (uint32_t)__bfloat16_as_ushort(hx);
    lo = ((uint32_t)__bfloat16_as_ushort(ly) << 16) | (uint32_t)__bfloat16_as_ushort(lx);
}

// ================= bf16-split tensor-core GEMM (R10 structure, unchanged) =================
#define SROWB   80
#define MATB    (128 * SROWB)       // 10240
#define STG_BYTES (4 * MATB)        // 40960

#define LOAD_STAGE(bufbase, k0)                                                       \
    _Pragma("unroll")                                                                 \
    for (int q = 0; q < 8; q++) {                                                     \
        int c = tid + q * 256;                                                        \
        int mat = c >> 9, row = (c >> 2) & 127, cc = c & 3;                           \
        uint32_t dstp = (bufbase) + mat * MATB + row * SROWB + cc * 16;               \
        const __nv_bfloat16* srcp;                                                    \
        if (mat == 0)      srcp = Ahi + (size_t)(mtile * 128 + row) * K + (k0) + cc * 8; \
        else if (mat == 1) srcp = Alo + (size_t)(mtile * 128 + row) * K + (k0) + cc * 8; \
        else if (mat == 2) srcp = Bhi + (size_t)(ntile * 128 + row) * K + (k0) + cc * 8; \
        else               srcp = Blo + (size_t)(ntile * 128 + row) * K + (k0) + cc * 8; \
        CP_ASYNC16(dstp, srcp);                                                       \
    }

__global__ __launch_bounds__(256, 2) void k_mma_gemm(const __nv_bfloat16* __restrict__ Ahi,
                                                     const __nv_bfloat16* __restrict__ Alo,
                                                     const __nv_bfloat16* __restrict__ Bhi,
                                                     const __nv_bfloat16* __restrict__ Blo,
                                                     float* __restrict__ C,
                                                     int M, int K, int N) {
    extern __shared__ char smem[];
    const int tid = threadIdx.x;
    const int lane = tid & 31, wid = tid >> 5;
    const int wm = (wid & 1) * 64, wn = (wid >> 1) * 32;
    const int mtile = blockIdx.y, ntile = blockIdx.x;
    const int nstages = K >> 5;
    const uint32_t sb = smem_u32(smem);

    float acc[4][4][4];
#pragma unroll
    for (int i = 0; i < 4; i++)
#pragma unroll
        for (int j = 0; j < 4; j++)
#pragma unroll
            for (int t = 0; t < 4; t++) acc[i][j][t] = 0.f;

    LOAD_STAGE(sb, 0);
    CP_COMMIT();

    const int ar = lane & 15, ac = (lane >> 4) * 8;
    const int bnr = ((lane >> 4) * 8) + (lane & 7);
    const int bkc = ((lane >> 3) & 1) * 8;

    for (int s = 0; s < nstages; s++) {
        if (s + 1 < nstages) {
            LOAD_STAGE(sb + (uint32_t)(((s + 1) & 1) * STG_BYTES), (s + 1) * 32);
            CP_COMMIT();
            CP_WAIT1();
        } else {
            CP_WAIT0();
        }
        __syncthreads();
        const uint32_t st = sb + (uint32_t)((s & 1) * STG_BYTES);
#pragma unroll
        for (int ks = 0; ks < 2; ks++) {
            uint32_t bh[4][2], bl[4][2];
#pragma unroll
            for (int jp = 0; jp < 2; jp++) {
                uint32_t baddr = st + 2u * MATB +
                    (uint32_t)((wn + jp * 16 + bnr) * SROWB + (ks * 16 + bkc) * 2);
                ldsm_x4(bh[jp * 2][0], bh[jp * 2][1], bh[jp * 2 + 1][0], bh[jp * 2 + 1][1], baddr);
                ldsm_x4(bl[jp * 2][0], bl[jp * 2][1], bl[jp * 2 + 1][0], bl[jp * 2 + 1][1], baddr + MATB);
            }
#pragma unroll
            for (int i = 0; i < 4; i++) {
                uint32_t ah[4], al[4];
                uint32_t aaddr = st + (uint32_t)((wm + i * 16 + ar) * SROWB + (ks * 16 + ac) * 2);
                ldsm_x4(ah[0], ah[1], ah[2], ah[3], aaddr);
                ldsm_x4(al[0], al[1], al[2], al[3], aaddr + MATB);
#pragma unroll
                for (int j = 0; j < 4; j++) {
                    mma16816(acc[i][j], ah, bh[j]);
                    mma16816(acc[i][j], ah, bl[j]);
                    mma16816(acc[i][j], al, bh[j]);
                }
            }
        }
        __syncthreads();
    }
    const int r0 = lane >> 2, cq = (lane & 3) * 2;
#pragma unroll
    for (int i = 0; i < 4; i++) {
#pragma unroll
        for (int j = 0; j < 4; j++) {
            int gr = mtile * 128 + wm + i * 16 + r0;
            int gc = ntile * 128 + wn + j * 8 + cq;
            if (gr < M) *(float2*)&C[(size_t)gr * N + gc] = make_float2(acc[i][j][0], acc[i][j][1]);
            if (gr + 8 < M) *(float2*)&C[(size_t)(gr + 8) * N + gc] = make_float2(acc[i][j][2], acc[i][j][3]);
        }
    }
}

// ---------------- fused weight prep ----------------
#define PREP_W1 (DIN * DHID)
#define PREP_W4 (DHID * DIN)
#define PREP_W2 (DHID * DOUT)
__global__ void k_prep_all(const float* __restrict__ W1, const float* __restrict__ W4,
                           const float* __restrict__ W2) {
    int i = blockIdx.x * blockDim.x + threadIdx.x;
    if (i < PREP_W1) {
        int k = i / DHID, n = i % DHID;
        float x = W1[i];
        __nv_bfloat16 h = __float2bfloat16(x);
        g_w1t_hi[(size_t)n * DIN + k] = h;
        g_w1t_lo[(size_t)n * DIN + k] = __float2bfloat16(x - __bfloat162float(h));
    } else if (i < PREP_W1 + PREP_W4) {
        int j = i - PREP_W1;
        int k = j / DIN, n = j % DIN;
        float x = W4[j];
        __nv_bfloat16 h = __float2bfloat16(x);
        g_w4t_hi[(size_t)n * DHID + k] = h;
        g_w4t_lo[(size_t)n * DHID + k] = __float2bfloat16(x - __bfloat162float(h));
    } else if (i < PREP_W1 + PREP_W4 + PREP_W2) {
        int j = i - PREP_W1 - PREP_W4;
        int col = j / DOUT, k = j % DOUT;
        g_w2t[k * DHID + col] = W2[j];
    }
}

// ---------------- A split: fp32 -> bf16 hi/lo ----------------
__global__ void k_split_a(const float* __restrict__ X, __nv_bfloat16* __restrict__ hi,
                          __nv_bfloat16* __restrict__ lo, int n2) {
    int i = blockIdx.x * blockDim.x + threadIdx.x;
    if (i >= n2) return;
    float2 v = ((const float2*)X)[i];
    uint32_t hp, lp;
    split2(v.x, v.y, hp, lp);
    ((uint32_t*)hi)[i] = hp;
    ((uint32_t*)lo)[i] = lp;
}

// ---------------- CSR build ----------------
__global__ void k_zero_deg() {
    int i = blockIdx.x * blockDim.x + threadIdx.x;
    if (i < N_NODES) g_deg[i] = 0;
}
__global__ void k_deg(const int* __restrict__ dst) {
    int e = blockIdx.x * blockDim.x + threadIdx.x;
    if (e < N_EDGES) atomicAdd(&g_deg[dst[e]], 1);
}
#define SCAN_T 1024
#define SCAN_CHUNK ((N_NODES + SCAN_T - 1) / SCAN_T)   // 49
__global__ __launch_bounds__(SCAN_T) void k_scan() {
    __shared__ int ps[SCAN_T];
    int t = threadIdx.x;
    int b0 = t * SCAN_CHUNK;
    int b1 = min(b0 + SCAN_CHUNK, N_NODES);
    int s = 0;
    for (int n = b0; n < b1; n++) s += g_deg[n];
    ps[t] = s;
    __syncthreads();
    for (int off = 1; off < SCAN_T; off <<= 1) {
        int v = ps[t];
        int add = (t >= off) ? ps[t - off] : 0;
        __syncthreads();
        ps[t] = v + add;
        __syncthreads();
    }
    int run = (t > 0) ? ps[t - 1] : 0;
    for (int n = b0; n < b1; n++) {
        g_off[n] = run;
        g_cur[n] = run;
        run += g_deg[n];
    }
    if (t == SCAN_T - 1) g_off[N_NODES] = run;
}
__global__ void k_fill(const int* __restrict__ src, const int* __restrict__ dst) {
    int e = blockIdx.x * blockDim.x + threadIdx.x;
    if (e >= N_EDGES) return;
    int slot = atomicAdd(&g_cur[dst[e]], 1);
    g_esrc[slot] = src[e];
    g_slot[e] = slot;
}

// ---------------- edge scores -> g_se[slot] ----------------
__global__ __launch_bounds__(256) void k_edge_score(const int* __restrict__ src,
                                                    const int* __restrict__ dst,
                                                    const float* __restrict__ h,
                                                    const float* __restrict__ att) {
    int e = (int)((blockIdx.x * (size_t)blockDim.x + threadIdx.x) >> 5);
    int lane = threadIdx.x & 31;
    if (e >= N_EDGES) return;
    int s = src[e], d = dst[e];
    const float4* hs = (const float4*)(h + (size_t)s * DHID);
    const float4* hd = (const float4*)(h + (size_t)d * DHID);
    const float4* at = (const float4*)att;
    float sum = 0.f;
#pragma unroll
    for (int i = 0; i < 4; i++) {
        int idx = lane + i * 32;
        float4 a = hs[idx], b = hd[idx], t = __ldg(&at[idx]);
        float x;
        x = a.x + b.x; sum += t.x * (x > 0.f ? x : NEG_SLOPE * x);
        x = a.y + b.y; sum += t.y * (x > 0.f ? x : NEG_SLOPE * x);
        x = a.z + b.z; sum += t.z * (x > 0.f ? x : NEG_SLOPE * x);
        x = a.w + b.w; sum += t.w * (x > 0.f ? x : NEG_SLOPE * x);
    }
#pragma unroll
    for (int o = 16; o > 0; o >>= 1) sum += __shfl_xor_sync(0xffffffffu, sum, o);
    if (lane == 0) g_se[g_slot[e]] = sum;
}

// ---------------- CSR gather-aggregation (512-wide, for conv1) ----------------
__global__ __launch_bounds__(256) void k_agg_csr(const float* __restrict__ X,
                                                 float* __restrict__ Out) {
    int node = (int)((blockIdx.x * (size_t)blockDim.x + threadIdx.x) >> 5);
    int lane = threadIdx.x & 31;
    if (node >= N_NODES) return;
    int off0 = g_off[node], off1 = g_off[node + 1];
    float4 a0 = make_float4(0.f, 0.f, 0.f, 0.f), a1 = a0, a2 = a0, a3 = a0;
    if (off1 > off0) {
        float m = __int_as_float(0xff800000);
        for (int j = off0 + lane; j < off1; j += 32) m = fmaxf(m, g_se[j]);
#pragma unroll
        for (int o = 16; o > 0; o >>= 1) m = fmaxf(m, __shfl_xor_sync(0xffffffffu, m, o));
        float ds = 0.f;
        for (int j = off0 + lane; j < off1; j += 32) ds += __expf(g_se[j] - m);
#pragma unroll
        for (int o = 16; o > 0; o >>= 1) ds += __shfl_xor_sync(0xffffffffu, ds, o);
        float inv = __fdividef(1.f, ds);
        for (int j = off0; j < off1; j++) {
            float w = __expf(g_se[j] - m);
            const float4* row = (const float4*)(X + (size_t)g_esrc[j] * DHID);
            float4 v;
            v = row[lane];       a0.x += w * v.x; a0.y += w * v.y; a0.z += w * v.z; a0.w += w * v.w;
            v = row[lane + 32];  a1.x += w * v.x; a1.y += w * v.y; a1.z += w * v.z; a1.w += w * v.w;
            v = row[lane + 64];  a2.x += w * v.x; a2.y += w * v.y; a2.z += w * v.z; a2.w += w * v.w;
            v = row[lane + 96];  a3.x += w * v.x; a3.y += w * v.y; a3.z += w * v.z; a3.w += w * v.w;
        }
        a0.x *= inv; a0.y *= inv; a0.z *= inv; a0.w *= inv;
        a1.x *= inv; a1.y *= inv; a1.z *= inv; a1.w *= inv;
        a2.x *= inv; a2.y *= inv; a2.z *= inv; a2.w *= inv;
        a3.x *= inv; a3.y *= inv; a3.z *= inv; a3.w *= inv;
    }
    float4* o = (float4*)(Out + (size_t)node * DHID);
    o[lane] = a0;
    o[lane + 32] = a1;
    o[lane + 64] = a2;
    o[lane + 96] = a3;
}

// ---------------- conv3 agg on 30-dim h2 rows (linearity: agg commutes with @W2^T) ----------------
__global__ __launch_bounds__(256) void k_agg30(const float* __restrict__ H2) {
    int node = (int)((blockIdx.x * (size_t)blockDim.x + threadIdx.x) >> 5);
    int lane = threadIdx.x & 31;
    if (node >= N_NODES) return;
    int off0 = g_off[node], off1 = g_off[node + 1];
    float acc = 0.f;
    if (off1 > off0) {
        float m = __int_as_float(0xff800000);
        for (int j = off0 + lane; j < off1; j += 32) m = fmaxf(m, g_se[j]);
#pragma unroll
        for (int o = 16; o > 0; o >>= 1) m = fmaxf(m, __shfl_xor_sync(0xffffffffu, m, o));
        float ds = 0.f;
        for (int j = off0 + lane; j < off1; j += 32) ds += __expf(g_se[j] - m);
#pragma unroll
        for (int o = 16; o > 0; o >>= 1) ds += __shfl_xor_sync(0xffffffffu, ds, o);
        float inv = __fdividef(1.f, ds);
        for (int j = off0; j < off1; j++) {
            float w = __expf(g_se[j] - m);
            if (lane < DOUT) acc += w * H2[(size_t)g_esrc[j] * DOUT + lane];
        }
        acc *= inv;
    }
    if (lane < 32) g_h2agg[node * 32 + lane] = (lane < DOUT) ? acc : 0.f;
}

// ---------------- h3 = elu(h2agg @ W2^T) -> bf16 hi/lo split (one block per node) ----------------
__global__ __launch_bounds__(256) void k_expand_elu_split(__nv_bfloat16* __restrict__ hi,
                                                          __nv_bfloat16* __restrict__ lo) {
    __shared__ float a[DOUT];
    int node = blockIdx.x;
    int t = threadIdx.x;
    if (t < DOUT) a[t] = g_h2agg[node * 32 + t];
    __syncthreads();
    int c0 = t * 2;
    float v0 = 0.f, v1 = 0.f;
#pragma unroll
    for (int k = 0; k < DOUT; k++) {
        float ak = a[k];
        v0 += ak * g_w2t[k * DHID + c0];
        v1 += ak * g_w2t[k * DHID + c0 + 1];
    }
    v0 = v0 > 0.f ? v0 : expm1f(v0);
    v1 = v1 > 0.f ? v1 : expm1f(v1);
    uint32_t hp, lp;
    split2(v0, v1, hp, lp);
    size_t idx = (size_t)node * (DHID / 2) + t;
    ((uint32_t*)hi)[idx] = hp;
    ((uint32_t*)lo)[idx] = lp;
}

// ---------------- h2 = elu(h1_norm) @ W2 ----------------
__global__ __launch_bounds__(256) void k_h2(const float* __restrict__ h1,
                                            const float* __restrict__ W2,
                                            float* __restrict__ out) {
    __shared__ float hs[8][DHID];
    const int tid = threadIdx.x;
    const int rowBase = blockIdx.x * 8;
    const float4* srcp = (const float4*)(h1 + (size_t)rowBase * DHID);
    float4* dstp = (float4*)hs;
    for (int i = tid; i < 8 * DHID / 4; i += 256) {
        float4 v = srcp[i];
        v.x = v.x > 0.f ? v.x : expm1f(v.x);
        v.y = v.y > 0.f ? v.y : expm1f(v.y);
        v.z = v.z > 0.f ? v.z : expm1f(v.z);
        v.w = v.w > 0.f ? v.w : expm1f(v.w);
        dstp[i] = v;
    }
    __syncthreads();
    int r = tid >> 5;
    int c = tid & 31;
    if (c < DOUT) {
        float acc = 0.f;
#pragma unroll 8
        for (int k = 0; k < DHID; k++) acc += hs[r][k] * __ldg(&W2[k * DOUT + c]);
        out[(size_t)(rowBase + r) * DOUT + c] = acc;
    }
}

// ---------------- launch ----------------
extern "C" void kernel_launch(void* const* d_in, const int* in_sizes, int n_in,
                              void* d_out, int out_size) {
    const float* features = (const float*)d_in[0];
    const int*   eidx     = (const int*)d_in[1];
    const float* W1       = (const float*)d_in[2];
    const float* att1     = (const float*)d_in[3];
    const float* W2       = (const float*)d_in[4];
    const float* W4       = (const float*)d_in[5];
    float* out = (float*)d_out;
    const int* src = eidx;
    const int* dst = eidx + N_EDGES;

    float *p_buf0, *p_buf1;
    __nv_bfloat16 *p_w1h, *p_w1l, *p_w4h, *p_w4l, *p_ah, *p_al;
    cudaGetSymbolAddress((void**)&p_buf0, g_buf0);
    cudaGetSymbolAddress((void**)&p_buf1, g_buf1);
    cudaGetSymbolAddress((void**)&p_w1h, g_w1t_hi);
    cudaGetSymbolAddress((void**)&p_w1l, g_w1t_lo);
    cudaGetSymbolAddress((void**)&p_w4h, g_w4t_hi);
    cudaGetSymbolAddress((void**)&p_w4l, g_w4t_lo);
    cudaGetSymbolAddress((void**)&p_ah, g_a_hi);
    cudaGetSymbolAddress((void**)&p_al, g_a_lo);

    cudaFuncSetAttribute(k_mma_gemm, cudaFuncAttributeMaxDynamicSharedMemorySize, 2 * STG_BYTES);

    float* out_h2 = out;                          // [50000, 30]
    float* out_h4 = out + (size_t)N_NODES * DOUT; // [50000, 1024]

    const int edgeBlocks = (N_EDGES * 32 + 255) / 256;
    const int nodeWarpBlocks = (N_NODES * 32 + 255) / 256;
    const int mtiles = (N_NODES + 127) / 128;     // 391

    // 1) zero degree counters
    k_zero_deg<<<(N_NODES + 255) / 256, 256>>>();
    // 2) all weight prep
    k_prep_all<<<(PREP_W1 + PREP_W4 + PREP_W2 + 255) / 256, 256>>>(W1, W4, W2);
    // 3) split features -> a_hi/a_lo
    k_split_a<<<(N_NODES * DIN / 2 + 255) / 256, 256>>>(features, p_ah, p_al, N_NODES * DIN / 2);
    // 4) h = X @ W1 -> buf0  (tensor cores; launch #4 -> ncu-profiled)
    {
        dim3 grid(DHID / 128, mtiles);
        k_mma_gemm<<<grid, 256, 2 * STG_BYTES>>>(p_ah, p_al, p_w1h, p_w1l, p_buf0, N_NODES, DIN, DHID);
    }
    // 5-7) CSR build
    k_deg<<<(N_EDGES + 255) / 256, 256>>>(dst);
    k_scan<<<1, SCAN_T>>>();
    k_fill<<<(N_EDGES + 255) / 256, 256>>>(src, dst);
    // 8) edge scores -> g_se[slot]
    k_edge_score<<<edgeBlocks, 256>>>(src, dst, p_buf0, att1);
    // 9) agg1 (CSR gather, 512-wide): buf1 = softmax-weighted mean of h rows
    k_agg_csr<<<nodeWarpBlocks, 256>>>(p_buf0, p_buf1);
    // 10) h2 = elu(buf1) @ W2 -> out
    k_h2<<<N_NODES / 8, 256>>>(p_buf1, W2, out_h2);
    // 11) agg2 on 30-dim h2 rows (aggregation commutes with @W2^T)
    k_agg30<<<nodeWarpBlocks, 256>>>(out_h2);
    // 12) h3 = elu(h2agg @ W2^T) -> bf16 split directly into a_hi/a_lo
    k_expand_elu_split<<<N_NODES, 256>>>(p_ah, p_al);
    // 13) h4 = h3 @ W4 -> out
    {
        dim3 grid(DIN / 128, mtiles);
        k_mma_gemm<<<grid, 256, 2 * STG_BYTES>>>(p_ah, p_al, p_w4h, p_w4l, out_h4, N_NODES, DHID, DIN);
    }
}

// round 16
// speedup vs baseline: 1.7097x; 1.0165x over previous
#include <cuda_runtime.h>
#include <cuda_bf16.h>
#include <cstdint>

#define N_NODES 50000
#define PAD_M   50048
#define N_EDGES 300000
#define DIN     1024
#define DHID    512
#define DOUT    30
#define NEG_SLOPE 0.2f
#define SCCAP   128

// ---------------- scratch (static device globals) ----------------
__device__ __align__(16) float g_buf0[N_NODES * DHID];   // h
__device__ float g_se[N_EDGES];          // edge scores, CSR(slot) order
__device__ int   g_deg[N_NODES];
__device__ int   g_off[N_NODES + 1];
__device__ int   g_cur[N_NODES];
__device__ int   g_esrc[N_EDGES];        // src node per slot
__device__ __align__(16) float g_w2t[DOUT * DHID];
// pre-transposed + bf16-split weights: [N][K] layout
__device__ __align__(16) __nv_bfloat16 g_w1t_hi[DHID * DIN];
__device__ __align__(16) __nv_bfloat16 g_w1t_lo[DHID * DIN];
__device__ __align__(16) __nv_bfloat16 g_w4t_hi[DIN * DHID];
__device__ __align__(16) __nv_bfloat16 g_w4t_lo[DIN * DHID];
// A-operand bf16 split (features K=1024, then h3 K=512); zero-initialized -> pad rows stay 0
__device__ __align__(16) __nv_bfloat16 g_a_hi[(size_t)PAD_M * DIN];
__device__ __align__(16) __nv_bfloat16 g_a_lo[(size_t)PAD_M * DIN];

// ================= helpers =================
__device__ __forceinline__ uint32_t smem_u32(const void* p) {
    uint32_t a;
    asm("{ .reg .u64 t; cvta.to.shared.u64 t, %1; cvt.u32.u64 %0, t; }" : "=r"(a) : "l"(p));
    return a;
}
#define CP_ASYNC16(dst, src) asm volatile("cp.async.cg.shared.global [%0], [%1], 16;" :: "r"(dst), "l"(src) : "memory")
#define CP_COMMIT()          asm volatile("cp.async.commit_group;" ::: "memory")
#define CP_WAIT1()           asm volatile("cp.async.wait_group 1;" ::: "memory")
#define CP_WAIT0()           asm volatile("cp.async.wait_group 0;" ::: "memory")

__device__ __forceinline__ void ldsm_x4(uint32_t& r0, uint32_t& r1, uint32_t& r2, uint32_t& r3, uint32_t a) {
    asm volatile("ldmatrix.sync.aligned.m8n8.x4.shared.b16 {%0,%1,%2,%3}, [%4];"
                 : "=r"(r0), "=r"(r1), "=r"(r2), "=r"(r3) : "r"(a));
}
__device__ __forceinline__ void mma16816(float* c, const uint32_t* a, const uint32_t* b) {
    asm volatile("mma.sync.aligned.m16n8k16.row.col.f32.bf16.bf16.f32 "
                 "{%0,%1,%2,%3}, {%4,%5,%6,%7}, {%8,%9}, {%0,%1,%2,%3};"
                 : "+f"(c[0]), "+f"(c[1]), "+f"(c[2]), "+f"(c[3])
                 : "r"(a[0]), "r"(a[1]), "r"(a[2]), "r"(a[3]), "r"(b[0]), "r"(b[1]));
}
__device__ __forceinline__ void split2(float x, float y, uint32_t& hi, uint32_t& lo) {
    __nv_bfloat16 hx = __float2bfloat16(x);
    __nv_bfloat16 hy = __float2bfloat16(y);
    __nv_bfloat16 lx = __float2bfloat16(x - __bfloat162float(hx));
    __nv_bfloat16 ly = __float2bfloat16(y - __bfloat162float(hy));
    hi = ((uint32_t)__bfloat16_as_ushort(hy) << 16) | (uint32_t)__bfloat16_as_ushort(hx);
    lo = ((uint32_t)__bfloat16_as_ushort(ly) << 16) | (uint32_t)__bfloat16_as_ushort(lx);
}

// ================= bf16-split tensor-core GEMM (R10 structure, unchanged) =================
#define SROWB   80
#define MATB    (128 * SROWB)       // 10240
#define STG_BYTES (4 * MATB)        // 40960

#define LOAD_STAGE(bufbase, k0)                                                       \
    _Pragma("unroll")                                                                 \
    for (int q = 0; q < 8; q++) {                                                     \
        int c = tid + q * 256;                                                        \
        int mat = c >> 9, row = (c >> 2) & 127, cc = c & 3;                           \
        uint32_t dstp = (bufbase) + mat * MATB + row * SROWB + cc * 16;               \
        const __nv_bfloat16* srcp;                                                    \
        if (mat == 0)      srcp = Ahi + (size_t)(mtile * 128 + row) * K + (k0) + cc * 8; \
        else if (mat == 1) srcp = Alo + (size_t)(mtile * 128 + row) * K + (k0) + cc * 8; \
        else if (mat == 2) srcp = Bhi + (size_t)(ntile * 128 + row) * K + (k0) + cc * 8; \
        else               srcp = Blo + (size_t)(ntile * 128 + row) * K + (k0) + cc * 8; \
        CP_ASYNC16(dstp, srcp);                                                       \
    }

__global__ __launch_bounds__(256, 2) void k_mma_gemm(const __nv_bfloat16* __restrict__ Ahi,
                                                     const __nv_bfloat16* __restrict__ Alo,
                                                     const __nv_bfloat16* __restrict__ Bhi,
                                                     const __nv_bfloat16* __restrict__ Blo,
                                                     float* __restrict__ C,
                                                     int M, int K, int N) {
    extern __shared__ char smem[];
    const int tid = threadIdx.x;
    const int lane = tid & 31, wid = tid >> 5;
    const int wm = (wid & 1) * 64, wn = (wid >> 1) * 32;
    const int mtile = blockIdx.y, ntile = blockIdx.x;
    const int nstages = K >> 5;
    const uint32_t sb = smem_u32(smem);

    float acc[4][4][4];
#pragma unroll
    for (int i = 0; i < 4; i++)
#pragma unroll
        for (int j = 0; j < 4; j++)
#pragma unroll
            for (int t = 0; t < 4; t++) acc[i][j][t] = 0.f;

    LOAD_STAGE(sb, 0);
    CP_COMMIT();

    const int ar = lane & 15, ac = (lane >> 4) * 8;
    const int bnr = ((lane >> 4) * 8) + (lane & 7);
    const int bkc = ((lane >> 3) & 1) * 8;

    for (int s = 0; s < nstages; s++) {
        if (s + 1 < nstages) {
            LOAD_STAGE(sb + (uint32_t)(((s + 1) & 1) * STG_BYTES), (s + 1) * 32);
            CP_COMMIT();
            CP_WAIT1();
        } else {
            CP_WAIT0();
        }
        __syncthreads();
        const uint32_t st = sb + (uint32_t)((s & 1) * STG_BYTES);
#pragma unroll
        for (int ks = 0; ks < 2; ks++) {
            uint32_t bh[4][2], bl[4][2];
#pragma unroll
            for (int jp = 0; jp < 2; jp++) {
                uint32_t baddr = st + 2u * MATB +
                    (uint32_t)((wn + jp * 16 + bnr) * SROWB + (ks * 16 + bkc) * 2);
                ldsm_x4(bh[jp * 2][0], bh[jp * 2][1], bh[jp * 2 + 1][0], bh[jp * 2 + 1][1], baddr);
                ldsm_x4(bl[jp * 2][0], bl[jp * 2][1], bl[jp * 2 + 1][0], bl[jp * 2 + 1][1], baddr + MATB);
            }
#pragma unroll
            for (int i = 0; i < 4; i++) {
                uint32_t ah[4], al[4];
                uint32_t aaddr = st + (uint32_t)((wm + i * 16 + ar) * SROWB + (ks * 16 + ac) * 2);
                ldsm_x4(ah[0], ah[1], ah[2], ah[3], aaddr);
                ldsm_x4(al[0], al[1], al[2], al[3], aaddr + MATB);
#pragma unroll
                for (int j = 0; j < 4; j++) {
                    mma16816(acc[i][j], ah, bh[j]);
                    mma16816(acc[i][j], ah, bl[j]);
                    mma16816(acc[i][j], al, bh[j]);
                }
            }
        }
        __syncthreads();
    }
    const int r0 = lane >> 2, cq = (lane & 3) * 2;
#pragma unroll
    for (int i = 0; i < 4; i++) {
#pragma unroll
        for (int j = 0; j < 4; j++) {
            int gr = mtile * 128 + wm + i * 16 + r0;
            int gc = ntile * 128 + wn + j * 8 + cq;
            if (gr < M) *(float2*)&C[(size_t)gr * N + gc] = make_float2(acc[i][j][0], acc[i][j][1]);
            if (gr + 8 < M) *(float2*)&C[(size_t)(gr + 8) * N + gc] = make_float2(acc[i][j][2], acc[i][j][3]);
        }
    }
}

// ---------------- fused weight prep ----------------
#define PREP_W1 (DIN * DHID)
#define PREP_W4 (DHID * DIN)
#define PREP_W2 (DHID * DOUT)
__global__ void k_prep_all(const float* __restrict__ W1, const float* __restrict__ W4,
                           const float* __restrict__ W2) {
    int i = blockIdx.x * blockDim.x + threadIdx.x;
    if (i < PREP_W1) {
        int k = i / DHID, n = i % DHID;
        float x = W1[i];
        __nv_bfloat16 h = __float2bfloat16(x);
        g_w1t_hi[(size_t)n * DIN + k] = h;
        g_w1t_lo[(size_t)n * DIN + k] = __float2bfloat16(x - __bfloat162float(h));
    } else if (i < PREP_W1 + PREP_W4) {
        int j = i - PREP_W1;
        int k = j / DIN, n = j % DIN;
        float x = W4[j];
        __nv_bfloat16 h = __float2bfloat16(x);
        g_w4t_hi[(size_t)n * DHID + k] = h;
        g_w4t_lo[(size_t)n * DHID + k] = __float2bfloat16(x - __bfloat162float(h));
    } else if (i < PREP_W1 + PREP_W4 + PREP_W2) {
        int j = i - PREP_W1 - PREP_W4;
        int col = j / DOUT, k = j % DOUT;
        g_w2t[k * DHID + col] = W2[j];
    }
}

// ---------------- A split: fp32 -> bf16 hi/lo ----------------
__global__ void k_split_a(const float* __restrict__ X, __nv_bfloat16* __restrict__ hi,
                          __nv_bfloat16* __restrict__ lo, int n2) {
    int i = blockIdx.x * blockDim.x + threadIdx.x;
    if (i >= n2) return;
    float2 v = ((const float2*)X)[i];
    uint32_t hp, lp;
    split2(v.x, v.y, hp, lp);
    ((uint32_t*)hi)[i] = hp;
    ((uint32_t*)lo)[i] = lp;
}

// ---------------- CSR build ----------------
__global__ void k_zero_deg() {
    int i = blockIdx.x * blockDim.x + threadIdx.x;
    if (i < N_NODES) g_deg[i] = 0;
}
__global__ void k_deg(const int* __restrict__ dst) {
    int e = blockIdx.x * blockDim.x + threadIdx.x;
    if (e < N_EDGES) atomicAdd(&g_deg[dst[e]], 1);
}
#define SCAN_T 1024
#define SCAN_CHUNK ((N_NODES + SCAN_T - 1) / SCAN_T)   // 49
__global__ __launch_bounds__(SCAN_T) void k_scan() {
    __shared__ int ps[SCAN_T];
    int t = threadIdx.x;
    int b0 = t * SCAN_CHUNK;
    int b1 = min(b0 + SCAN_CHUNK, N_NODES);
    int s = 0;
    for (int n = b0; n < b1; n++) s += g_deg[n];
    ps[t] = s;
    __syncthreads();
    for (int off = 1; off < SCAN_T; off <<= 1) {
        int v = ps[t];
        int add = (t >= off) ? ps[t - off] : 0;
        __syncthreads();
        ps[t] = v + add;
        __syncthreads();
    }
    int run = (t > 0) ? ps[t - 1] : 0;
    for (int n = b0; n < b1; n++) {
        g_off[n] = run;
        g_cur[n] = run;
        run += g_deg[n];
    }
    if (t == SCAN_T - 1) g_off[N_NODES] = run;
}
__global__ void k_fill(const int* __restrict__ src, const int* __restrict__ dst) {
    int e = blockIdx.x * blockDim.x + threadIdx.x;
    if (e >= N_EDGES) return;
    int slot = atomicAdd(&g_cur[dst[e]], 1);
    g_esrc[slot] = src[e];
}

// ---------------- warp score: att . leaky_relu(hs + hd), butterfly-reduced (uniform) ----------------
__device__ __forceinline__ float warp_score(const float4* __restrict__ r,
                                            const float4& d0, const float4& d1,
                                            const float4& d2, const float4& d3,
                                            const float4* att4, int lane) {
    float t = 0.f;
    float x;
    float4 hs, at;
    hs = r[lane];       at = att4[lane];
    x = hs.x + d0.x; t += at.x * (x > 0.f ? x : NEG_SLOPE * x);
    x = hs.y + d0.y; t += at.y * (x > 0.f ? x : NEG_SLOPE * x);
    x = hs.z + d0.z; t += at.z * (x > 0.f ? x : NEG_SLOPE * x);
    x = hs.w + d0.w; t += at.w * (x > 0.f ? x : NEG_SLOPE * x);
    hs = r[lane + 32];  at = att4[lane + 32];
    x = hs.x + d1.x; t += at.x * (x > 0.f ? x : NEG_SLOPE * x);
    x = hs.y + d1.y; t += at.y * (x > 0.f ? x : NEG_SLOPE * x);
    x = hs.z + d1.z; t += at.z * (x > 0.f ? x : NEG_SLOPE * x);
    x = hs.w + d1.w; t += at.w * (x > 0.f ? x : NEG_SLOPE * x);
    hs = r[lane + 64];  at = att4[lane + 64];
    x = hs.x + d2.x; t += at.x * (x > 0.f ? x : NEG_SLOPE * x);
    x = hs.y + d2.y; t += at.y * (x > 0.f ? x : NEG_SLOPE * x);
    x = hs.z + d2.z; t += at.z * (x > 0.f ? x : NEG_SLOPE * x);
    x = hs.w + d2.w; t += at.w * (x > 0.f ? x : NEG_SLOPE * x);
    hs = r[lane + 96];  at = att4[lane + 96];
    x = hs.x + d3.x; t += at.x * (x > 0.f ? x : NEG_SLOPE * x);
    x = hs.y + d3.y; t += at.y * (x > 0.f ? x : NEG_SLOPE * x);
    x = hs.z + d3.z; t += at.z * (x > 0.f ? x : NEG_SLOPE * x);
    x = hs.w + d3.w; t += at.w * (x > 0.f ? x : NEG_SLOPE * x);
#pragma unroll
    for (int o = 16; o > 0; o >>= 1) t += __shfl_xor_sync(0xffffffffu, t, o);
    return t;
}

// ---------------- conv1 fused: scores + softmax + aggregate + ELU + (@W2, 30 cols) ----------------
// One warp per node. Writes g_se (for conv3) and h2 (output).
__global__ __launch_bounds__(256) void k_conv1_fused(const float* __restrict__ h,
                                                     const float* __restrict__ att,
                                                     const float* __restrict__ W2,
                                                     float* __restrict__ h2out) {
    __shared__ float4 att4[128];
    __shared__ float4 vec4[8][128];
    __shared__ float  sc[8][SCCAP];
    const int tid = threadIdx.x, lane = tid & 31, wid = tid >> 5;
    if (tid < 128) att4[tid] = ((const float4*)att)[tid];
    __syncthreads();
    int node = blockIdx.x * 8 + wid;
    if (node >= N_NODES) return;
    const int off0 = g_off[node], off1 = g_off[node + 1], deg = off1 - off0;

    const float4* hrow = (const float4*)(h + (size_t)node * DHID);
    float4 d0 = hrow[lane], d1 = hrow[lane + 32], d2 = hrow[lane + 64], d3 = hrow[lane + 96];
    float4 a0 = make_float4(0.f, 0.f, 0.f, 0.f), a1 = a0, a2 = a0, a3 = a0;

    if (deg > 0) {
        float inv;
        if (deg <= SCCAP) {
            // pass 1: scores -> smem + g_se
            for (int j = 0; j < deg; j++) {
                const float4* r = (const float4*)(h + (size_t)g_esrc[off0 + j] * DHID);
                float t = warp_score(r, d0, d1, d2, d3, att4, lane);
                if (lane == 0) { sc[wid][j] = t; g_se[off0 + j] = t; }
            }
            __syncwarp();
            float m = __int_as_float(0xff800000);
            for (int j = lane; j < deg; j += 32) m = fmaxf(m, sc[wid][j]);
#pragma unroll
            for (int o = 16; o > 0; o >>= 1) m = fmaxf(m, __shfl_xor_sync(0xffffffffu, m, o));
            float ds = 0.f;
            for (int j = lane; j < deg; j += 32) ds += __expf(sc[wid][j] - m);
#pragma unroll
            for (int o = 16; o > 0; o >>= 1) ds += __shfl_xor_sync(0xffffffffu, ds, o);
            inv = __fdividef(1.f, ds);
            // pass 2: weighted gather (rows L2-hot)
            for (int j = 0; j < deg; j++) {
                float w = __expf(sc[wid][j] - m);
                const float4* r = (const float4*)(h + (size_t)g_esrc[off0 + j] * DHID);
                float4 v;
                v = r[lane];      a0.x += w * v.x; a0.y += w * v.y; a0.z += w * v.z; a0.w += w * v.w;
                v = r[lane + 32]; a1.x += w * v.x; a1.y += w * v.y; a1.z += w * v.z; a1.w += w * v.w;
                v = r[lane + 64]; a2.x += w * v.x; a2.y += w * v.y; a2.z += w * v.z; a2.w += w * v.w;
                v = r[lane + 96]; a3.x += w * v.x; a3.y += w * v.y; a3.z += w * v.z; a3.w += w * v.w;
            }
        } else {
            // fallback (astronomically rare): recompute scores
            float m = __int_as_float(0xff800000);
            for (int j = 0; j < deg; j++) {
                const float4* r = (const float4*)(h + (size_t)g_esrc[off0 + j] * DHID);
                float t = warp_score(r, d0, d1, d2, d3, att4, lane);
                if (lane == 0) g_se[off0 + j] = t;
                m = fmaxf(m, t);
            }
            float ds = 0.f;
            for (int j = 0; j < deg; j++) {
                const float4* r = (const float4*)(h + (size_t)g_esrc[off0 + j] * DHID);
                float t = warp_score(r, d0, d1, d2, d3, att4, lane);
                float w = __expf(t - m);
                ds += w;
                float4 v;
                v = r[lane];      a0.x += w * v.x; a0.y += w * v.y; a0.z += w * v.z; a0.w += w * v.w;
                v = r[lane + 32]; a1.x += w * v.x; a1.y += w * v.y; a1.z += w * v.z; a1.w += w * v.w;
                v = r[lane + 64]; a2.x += w * v.x; a2.y += w * v.y; a2.z += w * v.z; a2.w += w * v.w;
                v = r[lane + 96]; a3.x += w * v.x; a3.y += w * v.y; a3.z += w * v.z; a3.w += w * v.w;
            }
            inv = __fdividef(1.f, ds);
        }
        a0.x *= inv; a0.y *= inv; a0.z *= inv; a0.w *= inv;
        a1.x *= inv; a1.y *= inv; a1.z *= inv; a1.w *= inv;
        a2.x *= inv; a2.y *= inv; a2.z *= inv; a2.w *= inv;
        a3.x *= inv; a3.y *= inv; a3.z *= inv; a3.w *= inv;
    }
    // ELU
#define ELU4(v) { v.x = v.x > 0.f ? v.x : expm1f(v.x); v.y = v.y > 0.f ? v.y : expm1f(v.y); \
                  v.z = v.z > 0.f ? v.z : expm1f(v.z); v.w = v.w > 0.f ? v.w : expm1f(v.w); }
    ELU4(a0); ELU4(a1); ELU4(a2); ELU4(a3);
    vec4[wid][lane] = a0;
    vec4[wid][lane + 32] = a1;
    vec4[wid][lane + 64] = a2;
    vec4[wid][lane + 96] = a3;
    __syncwarp();
    // GEMV: 30 output cols
    if (lane < DOUT) {
        const float* v = (const float*)vec4[wid];
        float s = 0.f;
#pragma unroll 8
        for (int k = 0; k < DHID; k++) s += v[k] * __ldg(&W2[k * DOUT + lane]);
        h2out[(size_t)node * DOUT + lane] = s;
    }
}

// ---------------- conv3 fused: agg(30-dim h2) + expand @W2^T + ELU + bf16 split ----------------
// One warp per node; cols strided per lane for coalesced W2t reads & bf16 stores.
__global__ __launch_bounds__(256) void k_conv3_fused(const float* __restrict__ H2,
                                                     __nv_bfloat16* __restrict__ hi,
                                                     __nv_bfloat16* __restrict__ lo) {
    __shared__ float a30[8][32];
    const int tid = threadIdx.x, lane = tid & 31, wid = tid >> 5;
    int node = blockIdx.x * 8 + wid;
    if (node >= N_NODES) return;
    const int off0 = g_off[node], off1 = g_off[node + 1], deg = off1 - off0;
    float acc = 0.f;
    if (deg > 0) {
        float m = __int_as_float(0xff800000);
        for (int j = off0 + lane; j < off1; j += 32) m = fmaxf(m, g_se[j]);
#pragma unroll
        for (int o = 16; o > 0; o >>= 1) m = fmaxf(m, __shfl_xor_sync(0xffffffffu, m, o));
        float ds = 0.f;
        for (int j = off0 + lane; j < off1; j += 32) ds += __expf(g_se[j] - m);
#pragma unroll
        for (int o = 16; o > 0; o >>= 1) ds += __shfl_xor_sync(0xffffffffu, ds, o);
        float inv = __fdividef(1.f, ds);
        for (int j = off0; j < off1; j++) {
            float w = __expf(g_se[j] - m);
            if (lane < DOUT) acc += w * H2[(size_t)g_esrc[j] * DOUT + lane];
        }
        acc *= inv;
    }
    a30[wid][lane] = (lane < DOUT) ? acc : 0.f;
    __syncwarp();
    const float* a = a30[wid];
#pragma unroll
    for (int q = 0; q < 16; q++) {
        int c = lane + q * 32;
        float s = 0.f;
#pragma unroll
        for (int k = 0; k < DOUT; k++) s += a[k] * g_w2t[k * DHID + c];
        s = s > 0.f ? s : expm1f(s);
        __nv_bfloat16 hb = __float2bfloat16(s);
        __nv_bfloat16 lb = __float2bfloat16(s - __bfloat162float(hb));
        size_t idx = (size_t)node * DHID + c;
        hi[idx] = hb;
        lo[idx] = lb;
    }
}

// ---------------- launch ----------------
extern "C" void kernel_launch(void* const* d_in, const int* in_sizes, int n_in,
                              void* d_out, int out_size) {
    const float* features = (const float*)d_in[0];
    const int*   eidx     = (const int*)d_in[1];
    const float* W1       = (const float*)d_in[2];
    const float* att1     = (const float*)d_in[3];
    const float* W2       = (const float*)d_in[4];
    const float* W4       = (const float*)d_in[5];
    float* out = (float*)d_out;
    const int* src = eidx;
    const int* dst = eidx + N_EDGES;

    float* p_buf0;
    __nv_bfloat16 *p_w1h, *p_w1l, *p_w4h, *p_w4l, *p_ah, *p_al;
    cudaGetSymbolAddress((void**)&p_buf0, g_buf0);
    cudaGetSymbolAddress((void**)&p_w1h, g_w1t_hi);
    cudaGetSymbolAddress((void**)&p_w1l, g_w1t_lo);
    cudaGetSymbolAddress((void**)&p_w4h, g_w4t_hi);
    cudaGetSymbolAddress((void**)&p_w4l, g_w4t_lo);
    cudaGetSymbolAddress((void**)&p_ah, g_a_hi);
    cudaGetSymbolAddress((void**)&p_al, g_a_lo);

    cudaFuncSetAttribute(k_mma_gemm, cudaFuncAttributeMaxDynamicSharedMemorySize, 2 * STG_BYTES);

    float* out_h2 = out;                          // [50000, 30]
    float* out_h4 = out + (size_t)N_NODES * DOUT; // [50000, 1024]

    const int nodeBlocks = (N_NODES + 7) / 8;     // warp per node, 8 warps/block
    const int mtiles = (N_NODES + 127) / 128;     // 391

    // 1) zero degree counters
    k_zero_deg<<<(N_NODES + 255) / 256, 256>>>();
    // 2) all weight prep
    k_prep_all<<<(PREP_W1 + PREP_W4 + PREP_W2 + 255) / 256, 256>>>(W1, W4, W2);
    // 3) split features -> a_hi/a_lo
    k_split_a<<<(N_NODES * DIN / 2 + 255) / 256, 256>>>(features, p_ah, p_al, N_NODES * DIN / 2);
    // 4) h = X @ W1 -> buf0  (tensor cores; launch #4 -> ncu-profiled)
    {
        dim3 grid(DHID / 128, mtiles);
        k_mma_gemm<<<grid, 256, 2 * STG_BYTES>>>(p_ah, p_al, p_w1h, p_w1l, p_buf0, N_NODES, DIN, DHID);
    }
    // 5-7) CSR build
    k_deg<<<(N_EDGES + 255) / 256, 256>>>(dst);
    k_scan<<<1, SCAN_T>>>();
    k_fill<<<(N_EDGES + 255) / 256, 256>>>(src, dst);
    // 8) conv1 fused: scores + softmax + aggregate + ELU + @W2 -> h2; writes g_se
    k_conv1_fused<<<nodeBlocks, 256>>>(p_buf0, att1, W2, out_h2);
    // 9) conv3 fused: agg(h2) + expand @W2^T + ELU + bf16 split -> a_hi/a_lo
    k_conv3_fused<<<nodeBlocks, 256>>>(out_h2, p_ah, p_al);
    // 10) h4 = h3 @ W4 -> out
    {
        dim3 grid(DIN / 128, mtiles);
        k_mma_gemm<<<grid, 256, 2 * STG_BYTES>>>(p_ah, p_al, p_w4h, p_w4l, out_h4, N_NODES, DHID, DIN);
    }
}